// round 2
// baseline (speedup 1.0000x reference)
#include <cuda_runtime.h>
#include <cuda_bf16.h>
#include <math.h>

#define NTOK   16384
#define TLEN   2048
#define DMODEL 768
#define DINNER 1536
#define DSTATE 64
#define NHEADS 24
#define CONVDIM 1664
#define DINPROJ 3224
#define NCHUNK 32
#define NBLK_SSD (8*NCHUNK*NHEADS)   /* 6144 */
#define SMP 65

// ------------------------- scratch (device globals) -------------------------
__device__ float g_hmid[(size_t)NTOK*128];
__device__ float g_h   [(size_t)NTOK*DMODEL];
__device__ float g_zx  [(size_t)NTOK*DINPROJ];
__device__ float g_xBC [(size_t)NTOK*CONVDIM];
__device__ float g_dt  [(size_t)NTOK*NHEADS];
__device__ float g_ys  [(size_t)NTOK*DINNER];
__device__ float g_yg  [(size_t)NTOK*DINNER];
__device__ float g_y2  [(size_t)NTOK*DMODEL];
__device__ float g_S   [(size_t)NBLK_SSD*4096];
__device__ float g_seg [(size_t)NBLK_SSD*64];
__device__ float g_cd  [NBLK_SSD];
__device__ float g_wt  [(size_t)(3+9+27)*128*256];

// ------------------------- helpers -------------------------
__device__ __forceinline__ float blockReduceSum(float v, float* red) {
    int tid = threadIdx.x;
    #pragma unroll
    for (int o = 16; o; o >>= 1) v += __shfl_xor_sync(0xffffffffu, v, o);
    if ((tid & 31) == 0) red[tid >> 5] = v;
    __syncthreads();
    if (tid < 32) {
        float w = (tid < 8) ? red[tid] : 0.f;
        #pragma unroll
        for (int o = 4; o; o >>= 1) w += __shfl_xor_sync(0xffffffffu, w, o);
        if (tid == 0) red[0] = w;
    }
    __syncthreads();
    float r0 = red[0];
    __syncthreads();
    return r0;
}

// ------------------------- generic NT SGEMM, 128x128x8 tiles -------------------------
// C[M][N] = A[M][K] * B[N][K]^T.  M multiple of 128. ldA=K, ldB=K, ldC=N.
// epi: 0 = plain store, 1 = silu(acc + bias[n])
__global__ __launch_bounds__(256) void gemm128_nt(
    const float* __restrict__ A, const float* __restrict__ B,
    float* __restrict__ C, int N, int K,
    const float* __restrict__ bias, int epi)
{
    __shared__ float As[8][128];
    __shared__ float Bs[8][128];
    int m0 = blockIdx.y * 128, n0 = blockIdx.x * 128;
    int tid = threadIdx.x;
    int tx = tid & 15, ty = tid >> 4;
    float acc[8][8] = {};
    int lr = tid >> 1;
    int lk = (tid & 1) * 4;
    const float* Ag = A + (size_t)(m0 + lr) * K + lk;
    const float* Bg = B + (size_t)(n0 + lr) * K + lk;
    bool bvalid = (n0 + lr) < N;
    for (int k0 = 0; k0 < K; k0 += 8) {
        float4 av = *(const float4*)(Ag + k0);
        float4 bv = bvalid ? *(const float4*)(Bg + k0) : make_float4(0.f,0.f,0.f,0.f);
        __syncthreads();
        As[lk+0][lr] = av.x; As[lk+1][lr] = av.y; As[lk+2][lr] = av.z; As[lk+3][lr] = av.w;
        Bs[lk+0][lr] = bv.x; Bs[lk+1][lr] = bv.y; Bs[lk+2][lr] = bv.z; Bs[lk+3][lr] = bv.w;
        __syncthreads();
        #pragma unroll
        for (int kk = 0; kk < 8; kk++) {
            float4 a0 = *(const float4*)&As[kk][ty*8];
            float4 a1 = *(const float4*)&As[kk][ty*8+4];
            float4 b0 = *(const float4*)&Bs[kk][tx*8];
            float4 b1 = *(const float4*)&Bs[kk][tx*8+4];
            float a[8] = {a0.x,a0.y,a0.z,a0.w,a1.x,a1.y,a1.z,a1.w};
            float b[8] = {b0.x,b0.y,b0.z,b0.w,b1.x,b1.y,b1.z,b1.w};
            #pragma unroll
            for (int r = 0; r < 8; r++)
                #pragma unroll
                for (int s = 0; s < 8; s++) acc[r][s] += a[r]*b[s];
        }
    }
    #pragma unroll
    for (int r = 0; r < 8; r++) {
        int m = m0 + ty*8 + r;
        #pragma unroll
        for (int s = 0; s < 8; s++) {
            int n = n0 + tx*8 + s;
            if (n < N) {
                float v = acc[r][s];
                if (epi == 1) { v += bias[n]; v = v / (1.f + expf(-v)); }
                C[(size_t)m * N + n] = v;
            }
        }
    }
}

// ------------------------- front conv weight transpose -------------------------
// w[o][i][k] (256,128,K) -> wt[(k*128+i)*256 + o]
__global__ void transpose_w(const float* __restrict__ w, float* __restrict__ wt, int KTAP)
{
    int idx = blockIdx.x * 256 + threadIdx.x;
    int total = 256 * 128 * KTAP;
    if (idx >= total) return;
    int o = idx & 255;
    int rest = idx >> 8;
    int i = rest & 127;
    int k = rest >> 7;
    wt[idx] = w[(size_t)o * 128 * KTAP + (size_t)i * KTAP + k];
}

// ------------------------- front conv: 64 tok x 64 out tile, loop over taps -------------------------
template<int KTAP>
__global__ __launch_bounds__(256) void conv_front(
    const float* __restrict__ hmid, const float* __restrict__ wt,
    const float* __restrict__ bias, float* __restrict__ out, int colofs)
{
    const int PAD = KTAP / 2;
    __shared__ float As[16*64];
    __shared__ float Bs[16*64];
    int t0 = blockIdx.y * 64;
    int o0 = blockIdx.x * 64;
    int tid = threadIdx.x;
    int tx = tid & 15, ty = tid >> 4;
    float acc[4][4] = {};
    int tib0 = t0 & (TLEN - 1);
    for (int k = 0; k < KTAP; k++) {
        for (int kc = 0; kc < 8; kc++) {
            __syncthreads();
            #pragma unroll
            for (int e = tid; e < 1024; e += 256) {
                int ii = e & 15, tt = e >> 4;
                int ti = tib0 + tt + k - PAD;
                float v = 0.f;
                if (ti >= 0 && ti < TLEN)
                    v = hmid[(size_t)(t0 + tt + k - PAD) * 128 + kc*16 + ii];
                As[ii*64 + tt] = v;
            }
            #pragma unroll
            for (int e = tid; e < 1024; e += 256) {
                int oo = e & 63, ii = e >> 6;
                Bs[ii*64 + oo] = wt[(size_t)(k*128 + kc*16 + ii) * 256 + o0 + oo];
            }
            __syncthreads();
            #pragma unroll
            for (int ii = 0; ii < 16; ii++) {
                float4 a = *(const float4*)&As[ii*64 + ty*4];
                float4 b = *(const float4*)&Bs[ii*64 + tx*4];
                float av[4] = {a.x,a.y,a.z,a.w};
                float bv[4] = {b.x,b.y,b.z,b.w};
                #pragma unroll
                for (int r = 0; r < 4; r++)
                    #pragma unroll
                    for (int s = 0; s < 4; s++) acc[r][s] += av[r]*bv[s];
            }
        }
    }
    #pragma unroll
    for (int r = 0; r < 4; r++)
        #pragma unroll
        for (int s = 0; s < 4; s++) {
            int t = t0 + ty*4 + r, o = o0 + tx*4 + s;
            float v = acc[r][s] + bias[o];
            v = v / (1.f + expf(-v));
            out[(size_t)t * DMODEL + colofs + o] = v;
        }
}

// ------------------------- dt = softplus(zx[...,3200+h] + dt_bias) -------------------------
__global__ void dt_softplus(const float* __restrict__ zx, const float* __restrict__ dtb,
                            float* __restrict__ dt)
{
    int idx = blockIdx.x * 256 + threadIdx.x;
    if (idx >= NTOK * NHEADS) return;
    int t = idx / NHEADS, hh = idx - t * NHEADS;
    float x = zx[(size_t)t * DINPROJ + 3200 + hh] + dtb[hh];
    dt[idx] = (x > 20.f) ? x : log1pf(expf(x));
}

// ------------------------- depthwise causal conv (K=4) + silu -------------------------
__global__ void dwconv(const float* __restrict__ zx, const float* __restrict__ cw,
                       const float* __restrict__ cb, float* __restrict__ xBC)
{
    int c = blockIdx.x * 256 + threadIdx.x;
    int t = blockIdx.y;
    if (c >= CONVDIM) return;
    int ti = t & (TLEN - 1);
    float4 w = *(const float4*)(cw + (size_t)c * 4);
    float wk[4] = {w.x, w.y, w.z, w.w};
    float acc = cb[c];
    #pragma unroll
    for (int k = 0; k < 4; k++) {
        int tj = ti - 3 + k;
        if (tj >= 0) acc += zx[(size_t)(t - 3 + k) * DINPROJ + DINNER + c] * wk[k];
    }
    xBC[(size_t)t * CONVDIM + c] = acc / (1.f + expf(-acc));
}

// ------------------------- SSD per-chunk kernel -------------------------
__global__ __launch_bounds__(256) void ssd_chunk(
    const float* __restrict__ xBC, const float* __restrict__ dt,
    const float* __restrict__ A_log, const float* __restrict__ Dv,
    float* __restrict__ ys, float* __restrict__ Sg,
    float* __restrict__ segout, float* __restrict__ cdout)
{
    extern __shared__ float sm[];
    float* Bs  = sm;             // 64*65
    float* Cs  = Bs + 64*SMP;    // 64*65 (later reused for att)
    float* Ds  = Cs + 64*SMP;    // 64*65
    float* seg = Ds + 64*SMP;    // 64
    float* dec = seg + 64;       // 64
    float* dts = dec + 64;       // 64

    int blk = blockIdx.x;
    int h = blk % NHEADS;
    int c = (blk / NHEADS) & (NCHUNK - 1);
    int b = blk / (NHEADS * NCHUNK);
    int t0 = b * TLEN + c * 64;
    int tid = threadIdx.x;
    float A = -expf(A_log[h]);

    if (tid < 64) dts[tid] = dt[(size_t)(t0 + tid) * NHEADS + h];
    __syncthreads();
    for (int e = tid; e < 4096; e += 256) {
        int j = e >> 6, n = e & 63;
        const float* row = xBC + (size_t)(t0 + j) * CONVDIM;
        Bs[j*SMP + n] = row[DINNER + n];
        Cs[j*SMP + n] = row[DINNER + DSTATE + n];
        Ds[j*SMP + n] = dts[j] * row[h*64 + n];
    }
    if (tid < 64) seg[tid] = dts[tid] * A;
    __syncthreads();
    for (int off = 1; off < 64; off <<= 1) {
        float v = 0.f;
        bool act = (tid < 64) && (tid >= off);
        if (act) v = seg[tid - off];
        __syncthreads();
        if (act) seg[tid] += v;
        __syncthreads();
    }
    if (tid < 64) {
        dec[tid] = expf(seg[63] - seg[tid]);
        segout[(size_t)blk * 64 + tid] = seg[tid];
    }
    if (tid == 0) cdout[blk] = expf(seg[63]);
    __syncthreads();

    int tx = tid & 15, ty = tid >> 4;
    // ---- scores[i][j] = sum_n Cr[i][n]*Br[j][n]
    float acc[4][4] = {};
    #pragma unroll 4
    for (int n = 0; n < 64; n++) {
        float a[4], bb[4];
        #pragma unroll
        for (int r = 0; r < 4; r++) a[r] = Cs[(ty*4 + r)*SMP + n];
        #pragma unroll
        for (int s = 0; s < 4; s++) bb[s] = Bs[(tx*4 + s)*SMP + n];
        #pragma unroll
        for (int r = 0; r < 4; r++)
            #pragma unroll
            for (int s = 0; s < 4; s++) acc[r][s] += a[r]*bb[s];
    }
    __syncthreads();
    // ---- att into Cs (reuse)
    #pragma unroll
    for (int r = 0; r < 4; r++)
        #pragma unroll
        for (int s = 0; s < 4; s++) {
            int i = ty*4 + r, j = tx*4 + s;
            float v = 0.f;
            if (i >= j) v = expf(seg[i] - seg[j]) * acc[r][s];
            Cs[i*SMP + j] = v;
        }
    __syncthreads();
    // ---- y[i][p] = sum_j att[i][j]*dtx[j][p]   (+ D*xs)
    float acc2[4][4] = {};
    #pragma unroll 4
    for (int j = 0; j < 64; j++) {
        float a[4], bb[4];
        #pragma unroll
        for (int r = 0; r < 4; r++) a[r] = Cs[(ty*4 + r)*SMP + j];
        #pragma unroll
        for (int s = 0; s < 4; s++) bb[s] = Ds[j*SMP + tx*4 + s];
        #pragma unroll
        for (int r = 0; r < 4; r++)
            #pragma unroll
            for (int s = 0; s < 4; s++) acc2[r][s] += a[r]*bb[s];
    }
    float Dh = Dv[h];
    #pragma unroll
    for (int r = 0; r < 4; r++)
        #pragma unroll
        for (int s = 0; s < 4; s++) {
            int i = t0 + ty*4 + r;
            int p = tx*4 + s;
            ys[(size_t)i * DINNER + h*64 + p] =
                acc2[r][s] + Dh * xBC[(size_t)i * CONVDIM + h*64 + p];
        }
    // ---- S[p][n] = sum_j dec[j]*dtx[j][p]*Br[j][n]
    float acc3[4][4] = {};
    #pragma unroll 4
    for (int j = 0; j < 64; j++) {
        float dj = dec[j];
        float a[4], bb[4];
        #pragma unroll
        for (int r = 0; r < 4; r++) a[r] = Ds[j*SMP + ty*4 + r] * dj;
        #pragma unroll
        for (int s = 0; s < 4; s++) bb[s] = Bs[j*SMP + tx*4 + s];
        #pragma unroll
        for (int r = 0; r < 4; r++)
            #pragma unroll
            for (int s = 0; s < 4; s++) acc3[r][s] += a[r]*bb[s];
    }
    #pragma unroll
    for (int r = 0; r < 4; r++)
        #pragma unroll
        for (int s = 0; s < 4; s++)
            Sg[(size_t)blk * 4096 + (ty*4 + r)*64 + tx*4 + s] = acc3[r][s];
}

// ------------------------- sequential inter-chunk scan (S -> Hstarts, in place) -------------------------
__global__ __launch_bounds__(256) void ssd_scan(float* __restrict__ Sg,
                                                const float* __restrict__ cd)
{
    int blk = blockIdx.x;           // 192 = 8*24
    int h = blk % NHEADS, b = blk / NHEADS;
    int tid = threadIdx.x;
    float st[16];
    #pragma unroll
    for (int r = 0; r < 16; r++) st[r] = 0.f;
    for (int c = 0; c < NCHUNK; c++) {
        int bidx = (b * NCHUNK + c) * NHEADS + h;
        size_t base = (size_t)bidx * 4096;
        float d = cd[bidx];
        #pragma unroll
        for (int r = 0; r < 16; r++) {
            int e = tid + r*256;
            float s_in = Sg[base + e];
            float prev = st[r];
            st[r] = prev * d + s_in;
            Sg[base + e] = prev;
        }
    }
}

// ------------------------- y_inter accumulation -------------------------
__global__ __launch_bounds__(256) void ssd_inter(
    const float* __restrict__ xBC, const float* __restrict__ Sg,
    const float* __restrict__ segin, float* __restrict__ ys)
{
    __shared__ float Cs[64*SMP];
    __shared__ float Hs[64*SMP];
    __shared__ float seg[64];
    int blk = blockIdx.x;
    int h = blk % NHEADS;
    int c = (blk / NHEADS) & (NCHUNK - 1);
    int b = blk / (NHEADS * NCHUNK);
    int t0 = b * TLEN + c * 64;
    int tid = threadIdx.x;
    for (int e = tid; e < 4096; e += 256) {
        int j = e >> 6, n = e & 63;
        Cs[j*SMP + n] = xBC[(size_t)(t0 + j) * CONVDIM + DINNER + DSTATE + n];
        Hs[j*SMP + n] = Sg[(size_t)blk * 4096 + j*64 + n];
    }
    if (tid < 64) seg[tid] = segin[(size_t)blk * 64 + tid];
    __syncthreads();
    int tx = tid & 15, ty = tid >> 4;
    float acc[4][4] = {};
    #pragma unroll 4
    for (int n = 0; n < 64; n++) {
        float a[4], bb[4];
        #pragma unroll
        for (int r = 0; r < 4; r++) a[r] = Cs[(ty*4 + r)*SMP + n];
        #pragma unroll
        for (int s = 0; s < 4; s++) bb[s] = Hs[(tx*4 + s)*SMP + n];
        #pragma unroll
        for (int r = 0; r < 4; r++)
            #pragma unroll
            for (int s = 0; s < 4; s++) acc[r][s] += a[r]*bb[s];
    }
    #pragma unroll
    for (int r = 0; r < 4; r++) {
        float ei = expf(seg[ty*4 + r]);
        #pragma unroll
        for (int s = 0; s < 4; s++) {
            size_t idx = (size_t)(t0 + ty*4 + r) * DINNER + h*64 + tx*4 + s;
            ys[idx] += acc[r][s] * ei;
        }
    }
}

// ------------------------- gating + RMSNorm -------------------------
__global__ __launch_bounds__(256) void gate_rms(
    const float* __restrict__ ys, const float* __restrict__ zx,
    const float* __restrict__ nw, float* __restrict__ yg)
{
    __shared__ float red[32];
    int t = blockIdx.x, tid = threadIdx.x;
    float v[6];
    float ss = 0.f;
    #pragma unroll
    for (int r = 0; r < 6; r++) {
        int i = tid + r*256;
        float z = zx[(size_t)t * DINPROJ + i];
        float val = ys[(size_t)t * DINNER + i] * (z / (1.f + expf(-z)));
        v[r] = val;
        ss += val*val;
    }
    ss = blockReduceSum(ss, red);
    float sc = rsqrtf(ss / (float)DINNER + 1e-5f);
    #pragma unroll
    for (int r = 0; r < 6; r++) {
        int i = tid + r*256;
        yg[(size_t)t * DINNER + i] = v[r] * sc * nw[i];
    }
}

// ------------------------- residual + layernorm (in place on h) -------------------------
__global__ __launch_bounds__(256) void resid_ln(
    const float* __restrict__ y2, float* __restrict__ hio,
    const float* __restrict__ w, const float* __restrict__ b)
{
    __shared__ float red[32];
    int t = blockIdx.x, tid = threadIdx.x;
    float v[3];
    float s = 0.f;
    #pragma unroll
    for (int r = 0; r < 3; r++) {
        int i = tid + r*256;
        v[r] = y2[(size_t)t * DMODEL + i] + hio[(size_t)t * DMODEL + i];
        s += v[r];
    }
    s = blockReduceSum(s, red);
    float mean = s / (float)DMODEL;
    float q = 0.f;
    #pragma unroll
    for (int r = 0; r < 3; r++) { v[r] -= mean; q += v[r]*v[r]; }
    q = blockReduceSum(q, red);
    float inv = rsqrtf(q / (float)DMODEL + 1e-5f);
    #pragma unroll
    for (int r = 0; r < 3; r++) {
        int i = tid + r*256;
        hio[(size_t)t * DMODEL + i] = v[r] * inv * w[i] + b[i];
    }
}

// ------------------------- final layernorm + logits -------------------------
__global__ __launch_bounds__(256) void head_kernel(
    const float* __restrict__ hin,
    const float* __restrict__ fw, const float* __restrict__ fb,
    const float* __restrict__ lw, const float* __restrict__ lb,
    float* __restrict__ out)
{
    __shared__ float red[32];
    __shared__ float buf[DMODEL];
    int t = blockIdx.x, tid = threadIdx.x;
    float v[3];
    float s = 0.f;
    #pragma unroll
    for (int r = 0; r < 3; r++) {
        int i = tid + r*256;
        v[r] = hin[(size_t)t * DMODEL + i];
        s += v[r];
    }
    s = blockReduceSum(s, red);
    float mean = s / (float)DMODEL;
    float q = 0.f;
    #pragma unroll
    for (int r = 0; r < 3; r++) { v[r] -= mean; q += v[r]*v[r]; }
    q = blockReduceSum(q, red);
    float inv = rsqrtf(q / (float)DMODEL + 1e-5f);
    #pragma unroll
    for (int r = 0; r < 3; r++) {
        int i = tid + r*256;
        buf[i] = v[r] * inv * fw[i] + fb[i];
    }
    __syncthreads();
    for (int cls = 0; cls < 10; cls++) {
        float p = 0.f;
        #pragma unroll
        for (int r = 0; r < 3; r++) {
            int i = tid + r*256;
            p += buf[i] * lw[(size_t)cls * DMODEL + i];
        }
        p = blockReduceSum(p, red);
        if (tid == 0) out[(size_t)t * 10 + cls] = p + lb[cls];
    }
}

// ------------------------- launch -------------------------
extern "C" void kernel_launch(void* const* d_in, const int* in_sizes, int n_in,
                              void* d_out, int out_size)
{
    const float* x       = (const float*)d_in[0];
    const float* pc_w    = (const float*)d_in[1];
    const float* pc_b    = (const float*)d_in[2];
    const float* c1_w    = (const float*)d_in[3];
    const float* c1_b    = (const float*)d_in[4];
    const float* c2_w    = (const float*)d_in[5];
    const float* c2_b    = (const float*)d_in[6];
    const float* c3_w    = (const float*)d_in[7];
    const float* c3_b    = (const float*)d_in[8];
    const float* in_proj = (const float*)d_in[9];
    const float* conv_w  = (const float*)d_in[10];
    const float* conv_b  = (const float*)d_in[11];
    const float* dt_bias = (const float*)d_in[12];
    const float* A_log   = (const float*)d_in[13];
    const float* Dvec    = (const float*)d_in[14];
    const float* norm_w  = (const float*)d_in[15];
    const float* out_proj= (const float*)d_in[16];
    const float* ln_w    = (const float*)d_in[17];
    const float* ln_b    = (const float*)d_in[18];
    const float* fn_w    = (const float*)d_in[19];
    const float* fn_b    = (const float*)d_in[20];
    const float* lo_w    = (const float*)d_in[21];
    const float* lo_b    = (const float*)d_in[22];
    float* out = (float*)d_out;

    float *hmid, *h, *zx, *xBC, *dtb, *ys, *yg, *y2, *S, *segb, *cdb, *wt;
    cudaGetSymbolAddress((void**)&hmid, g_hmid);
    cudaGetSymbolAddress((void**)&h,    g_h);
    cudaGetSymbolAddress((void**)&zx,   g_zx);
    cudaGetSymbolAddress((void**)&xBC,  g_xBC);
    cudaGetSymbolAddress((void**)&dtb,  g_dt);
    cudaGetSymbolAddress((void**)&ys,   g_ys);
    cudaGetSymbolAddress((void**)&yg,   g_yg);
    cudaGetSymbolAddress((void**)&y2,   g_y2);
    cudaGetSymbolAddress((void**)&S,    g_S);
    cudaGetSymbolAddress((void**)&segb, g_seg);
    cudaGetSymbolAddress((void**)&cdb,  g_cd);
    cudaGetSymbolAddress((void**)&wt,   g_wt);

    const int SSD_SMEM = (3 * 64 * SMP + 3 * 64) * (int)sizeof(float); // 50688 B
    cudaFuncSetAttribute(ssd_chunk, cudaFuncAttributeMaxDynamicSharedMemorySize, SSD_SMEM);

    // ---- front ----
    // 1x1 conv == NT GEMM (M=16384, N=128, K=64) + bias + silu
    gemm128_nt<<<dim3(1, NTOK/128), 256>>>(x, pc_w, hmid, 128, 64, pc_b, 1);
    transpose_w<<<(256*128*3  + 255)/256, 256>>>(c1_w, wt,               3);
    transpose_w<<<(256*128*9  + 255)/256, 256>>>(c2_w, wt + 3*128*256,   9);
    transpose_w<<<(256*128*27 + 255)/256, 256>>>(c3_w, wt + 12*128*256, 27);
    conv_front<3> <<<dim3(4, NTOK/64), 256>>>(hmid, wt,               c1_b, h, 0);
    conv_front<9> <<<dim3(4, NTOK/64), 256>>>(hmid, wt + 3*128*256,   c2_b, h, 256);
    conv_front<27><<<dim3(4, NTOK/64), 256>>>(hmid, wt + 12*128*256,  c3_b, h, 512);

    // ---- layers ----
    for (int l = 0; l < 4; l++) {
        gemm128_nt<<<dim3((DINPROJ + 127)/128, NTOK/128), 256>>>(
            h, in_proj + (size_t)l * DINPROJ * DMODEL, zx, DINPROJ, DMODEL, nullptr, 0);
        dt_softplus<<<(NTOK*NHEADS + 255)/256, 256>>>(zx, dt_bias + l*NHEADS, dtb);
        dwconv<<<dim3((CONVDIM + 255)/256, NTOK), 256>>>(
            zx, conv_w + (size_t)l * CONVDIM * 4, conv_b + (size_t)l * CONVDIM, xBC);
        ssd_chunk<<<NBLK_SSD, 256, SSD_SMEM>>>(
            xBC, dtb, A_log + l*NHEADS, Dvec + l*NHEADS, ys, S, segb, cdb);
        ssd_scan<<<8*NHEADS, 256>>>(S, cdb);
        ssd_inter<<<NBLK_SSD, 256>>>(xBC, S, segb, ys);
        gate_rms<<<NTOK, 256>>>(ys, zx, norm_w + (size_t)l * DINNER, yg);
        gemm128_nt<<<dim3(DMODEL/128, NTOK/128), 256>>>(
            yg, out_proj + (size_t)l * DMODEL * DINNER, y2, DMODEL, DINNER, nullptr, 0);
        resid_ln<<<NTOK, 256>>>(y2, h, ln_w + (size_t)l * DMODEL, ln_b + (size_t)l * DMODEL);
    }

    // ---- head ----
    head_kernel<<<NTOK, 256>>>(h, fn_w, fn_b, lo_w, lo_b, out);
    (void)in_sizes; (void)n_in; (void)out_size;
}

// round 4
// speedup vs baseline: 1.7457x; 1.7457x over previous
#include <cuda_runtime.h>
#include <cuda_bf16.h>
#include <cstdint>
#include <math.h>

#define NTOK   16384
#define TLEN   2048
#define DMODEL 768
#define DINNER 1536
#define DSTATE 64
#define NHEADS 24
#define CONVDIM 1664
#define DINPROJ 3224
#define NCHUNK 32
#define NBLK_SSD (8*NCHUNK*NHEADS)   /* 6144 */
#define SMP 65

// ------------------------- scratch (device globals) -------------------------
__device__ float g_hmid[(size_t)NTOK*128];
__device__ float g_h   [(size_t)NTOK*DMODEL];
__device__ float g_zx  [(size_t)NTOK*DINPROJ];
__device__ float g_xBC [(size_t)NTOK*CONVDIM];
__device__ float g_dt  [(size_t)NTOK*NHEADS];
__device__ float g_ys  [(size_t)NTOK*DINNER];
__device__ float g_yg  [(size_t)NTOK*DINNER];
__device__ float g_y2  [(size_t)NTOK*DMODEL];
__device__ float g_S   [(size_t)NBLK_SSD*4096];
__device__ float g_seg [(size_t)NBLK_SSD*64];
__device__ float g_cd  [NBLK_SSD];
__device__ float g_wt  [(size_t)(3+9+27)*128*256];
// bf16 split buffers
__device__ __nv_bfloat16 g_ahi[(size_t)NTOK*DINNER];
__device__ __nv_bfloat16 g_alo[(size_t)NTOK*DINNER];
__device__ __nv_bfloat16 g_wih[(size_t)4*DINPROJ*DMODEL];
__device__ __nv_bfloat16 g_wil[(size_t)4*DINPROJ*DMODEL];
__device__ __nv_bfloat16 g_woh[(size_t)4*DMODEL*DINNER];
__device__ __nv_bfloat16 g_wol[(size_t)4*DMODEL*DINNER];

// ------------------------- PTX helpers -------------------------
__device__ __forceinline__ uint32_t smem_u32(const void* p) {
    uint32_t a;
    asm("{ .reg .u64 t; cvta.to.shared.u64 t, %1; cvt.u32.u64 %0, t; }" : "=r"(a) : "l"(p));
    return a;
}
__device__ __forceinline__ void cp16z(uint32_t dst, const void* src, int srcsz) {
    asm volatile("cp.async.cg.shared.global [%0], [%1], 16, %2;" :: "r"(dst), "l"(src), "r"(srcsz));
}
__device__ __forceinline__ void ldsm4(uint32_t* r, uint32_t addr) {
    asm volatile("ldmatrix.sync.aligned.m8n8.x4.shared.b16 {%0,%1,%2,%3}, [%4];"
        : "=r"(r[0]), "=r"(r[1]), "=r"(r[2]), "=r"(r[3]) : "r"(addr));
}
__device__ __forceinline__ void mma16816(float* c, const uint32_t* a, const uint32_t* b) {
    asm volatile("mma.sync.aligned.m16n8k16.row.col.f32.bf16.bf16.f32 "
        "{%0,%1,%2,%3}, {%4,%5,%6,%7}, {%8,%9}, {%0,%1,%2,%3};"
        : "+f"(c[0]), "+f"(c[1]), "+f"(c[2]), "+f"(c[3])
        : "r"(a[0]), "r"(a[1]), "r"(a[2]), "r"(a[3]), "r"(b[0]), "r"(b[1]));
}

// ------------------------- split fp32 -> bf16 hi/lo -------------------------
__global__ void split_bf16(const float4* __restrict__ src,
                           __nv_bfloat16* __restrict__ hi,
                           __nv_bfloat16* __restrict__ lo, int n4)
{
    int i = blockIdx.x * 256 + threadIdx.x;
    if (i >= n4) return;
    float4 v = src[i];
    float vv[4] = {v.x, v.y, v.z, v.w};
    __nv_bfloat16 h4[4], l4[4];
    #pragma unroll
    for (int j = 0; j < 4; j++) {
        h4[j] = __float2bfloat16(vv[j]);
        l4[j] = __float2bfloat16(vv[j] - __bfloat162float(h4[j]));
    }
    uint2 hp, lp;
    hp.x = (uint32_t)*(uint16_t*)&h4[0] | ((uint32_t)*(uint16_t*)&h4[1] << 16);
    hp.y = (uint32_t)*(uint16_t*)&h4[2] | ((uint32_t)*(uint16_t*)&h4[3] << 16);
    lp.x = (uint32_t)*(uint16_t*)&l4[0] | ((uint32_t)*(uint16_t*)&l4[1] << 16);
    lp.y = (uint32_t)*(uint16_t*)&l4[2] | ((uint32_t)*(uint16_t*)&l4[3] << 16);
    *reinterpret_cast<uint2*>(hi + (size_t)i * 4) = hp;
    *reinterpret_cast<uint2*>(lo + (size_t)i * 4) = lp;
}

// ------------------------- mma.sync split-bf16 NT GEMM, 128x128 tile -------------------------
// C[M][N] = A[M][K] * B[N][K]^T in ~fp32 precision (AhBh + AhBl + AlBh).
// M multiple of 128, N multiple of 8, K multiple of 32.
// smem per stage: Ah,Al,Bh,Bl each 128 rows x 80 bytes (32 bf16 + 8 pad).
#define MG_PITCH 80
#define MG_MAT   10240            /* 128*80 */
#define MG_STAGE 40960            /* 4 matrices */

__device__ __forceinline__ void mg_load(
    uint32_t sbase,
    const __nv_bfloat16* __restrict__ Ah, const __nv_bfloat16* __restrict__ Al,
    const __nv_bfloat16* __restrict__ Bh, const __nv_bfloat16* __restrict__ Bl,
    int m0, int n0, int Ntot, int K, int c, int tid)
{
    #pragma unroll
    for (int j = 0; j < 2; j++) {
        int e = tid + j * 256;
        int r = e >> 2, seg = e & 3;
        uint32_t soff = (uint32_t)(r * MG_PITCH + seg * 16);
        size_t kof = (size_t)c * 32 + (size_t)seg * 8;
        size_t aoff = (size_t)(m0 + r) * K + kof;
        cp16z(sbase + soff,             Ah + aoff, 16);
        cp16z(sbase + MG_MAT + soff,    Al + aoff, 16);
        int nr = n0 + r;
        int sz = (nr < Ntot) ? 16 : 0;
        int nrc = (nr < Ntot) ? nr : 0;
        size_t boff = (size_t)nrc * K + kof;
        cp16z(sbase + 2*MG_MAT + soff,  Bh + boff, sz);
        cp16z(sbase + 3*MG_MAT + soff,  Bl + boff, sz);
    }
    asm volatile("cp.async.commit_group;" ::: "memory");
}

__global__ __launch_bounds__(256) void mma_gemm(
    const __nv_bfloat16* __restrict__ Ah, const __nv_bfloat16* __restrict__ Al,
    const __nv_bfloat16* __restrict__ Bh, const __nv_bfloat16* __restrict__ Bl,
    float* __restrict__ C, int Ntot, int K)
{
    extern __shared__ char smem[];
    uint32_t sb = smem_u32(smem);
    int tid = threadIdx.x, wid = tid >> 5, lane = tid & 31;
    int m0 = blockIdx.y * 128, n0 = blockIdx.x * 128;
    int wm = (wid >> 1) * 32;      // warp m offset in tile
    int wn = (wid & 1) * 64;       // warp n offset in tile

    float acc[2][8][4];
    #pragma unroll
    for (int a = 0; a < 2; a++)
        #pragma unroll
        for (int b = 0; b < 8; b++)
            #pragma unroll
            for (int q = 0; q < 4; q++) acc[a][b][q] = 0.f;

    int gr = lane >> 3, lr = lane & 7;
    int arow = (gr & 1) * 8 + lr;
    int acol = (gr >> 1) * 16;
    int brow = (gr >> 1) * 8 + lr;
    int bcol = (gr & 1) * 16;

    int nch = K >> 5;
    mg_load(sb, Ah, Al, Bh, Bl, m0, n0, Ntot, K, 0, tid);
    for (int c = 0; c < nch; c++) {
        if (c + 1 < nch) {
            mg_load(sb + ((c + 1) & 1) * MG_STAGE, Ah, Al, Bh, Bl, m0, n0, Ntot, K, c + 1, tid);
            asm volatile("cp.async.wait_group 1;" ::: "memory");
        } else {
            asm volatile("cp.async.wait_group 0;" ::: "memory");
        }
        __syncthreads();
        uint32_t base = sb + (uint32_t)(c & 1) * MG_STAGE;
        #pragma unroll
        for (int ks = 0; ks < 2; ks++) {
            uint32_t ah[2][4], al[2][4];
            #pragma unroll
            for (int mt = 0; mt < 2; mt++) {
                uint32_t off = (uint32_t)((wm + mt*16 + arow) * MG_PITCH + acol + ks*32);
                ldsm4(ah[mt], base + off);
                ldsm4(al[mt], base + MG_MAT + off);
            }
            uint32_t bh[4][4], bl[4][4];
            #pragma unroll
            for (int np = 0; np < 4; np++) {
                uint32_t off = (uint32_t)((wn + np*16 + brow) * MG_PITCH + bcol + ks*32);
                ldsm4(bh[np], base + 2*MG_MAT + off);
                ldsm4(bl[np], base + 3*MG_MAT + off);
            }
            #pragma unroll
            for (int mt = 0; mt < 2; mt++)
                #pragma unroll
                for (int np = 0; np < 4; np++) {
                    mma16816(acc[mt][2*np],   ah[mt], &bh[np][0]);
                    mma16816(acc[mt][2*np+1], ah[mt], &bh[np][2]);
                    mma16816(acc[mt][2*np],   ah[mt], &bl[np][0]);
                    mma16816(acc[mt][2*np+1], ah[mt], &bl[np][2]);
                    mma16816(acc[mt][2*np],   al[mt], &bh[np][0]);
                    mma16816(acc[mt][2*np+1], al[mt], &bh[np][2]);
                }
        }
        __syncthreads();
    }

    // epilogue: c frag m16n8 -> rows (lane>>2, +8), cols (lane&3)*2, +1
    int r4 = lane >> 2, c2 = (lane & 3) * 2;
    #pragma unroll
    for (int mt = 0; mt < 2; mt++) {
        int r = m0 + wm + mt*16 + r4;
        #pragma unroll
        for (int nt = 0; nt < 8; nt++) {
            int col = n0 + wn + nt*8 + c2;
            if (col < Ntot) {
                float* cc = acc[mt][nt];
                *(float2*)&C[(size_t)r * Ntot + col]       = make_float2(cc[0], cc[1]);
                *(float2*)&C[(size_t)(r + 8) * Ntot + col] = make_float2(cc[2], cc[3]);
            }
        }
    }
}

// ------------------------- helpers -------------------------
__device__ __forceinline__ float blockReduceSum(float v, float* red) {
    int tid = threadIdx.x;
    #pragma unroll
    for (int o = 16; o; o >>= 1) v += __shfl_xor_sync(0xffffffffu, v, o);
    if ((tid & 31) == 0) red[tid >> 5] = v;
    __syncthreads();
    if (tid < 32) {
        float w = (tid < 8) ? red[tid] : 0.f;
        #pragma unroll
        for (int o = 4; o; o >>= 1) w += __shfl_xor_sync(0xffffffffu, w, o);
        if (tid == 0) red[0] = w;
    }
    __syncthreads();
    float r0 = red[0];
    __syncthreads();
    return r0;
}

// ------------------------- small fp32 NT SGEMM (front 1x1) -------------------------
__global__ __launch_bounds__(256) void gemm128_nt(
    const float* __restrict__ A, const float* __restrict__ B,
    float* __restrict__ C, int N, int K,
    const float* __restrict__ bias, int epi)
{
    __shared__ float As[8][128];
    __shared__ float Bs[8][128];
    int m0 = blockIdx.y * 128, n0 = blockIdx.x * 128;
    int tid = threadIdx.x;
    int tx = tid & 15, ty = tid >> 4;
    float acc[8][8] = {};
    int lr = tid >> 1;
    int lk = (tid & 1) * 4;
    const float* Ag = A + (size_t)(m0 + lr) * K + lk;
    const float* Bg = B + (size_t)(n0 + lr) * K + lk;
    bool bvalid = (n0 + lr) < N;
    for (int k0 = 0; k0 < K; k0 += 8) {
        float4 av = *(const float4*)(Ag + k0);
        float4 bv = bvalid ? *(const float4*)(Bg + k0) : make_float4(0.f,0.f,0.f,0.f);
        __syncthreads();
        As[lk+0][lr] = av.x; As[lk+1][lr] = av.y; As[lk+2][lr] = av.z; As[lk+3][lr] = av.w;
        Bs[lk+0][lr] = bv.x; Bs[lk+1][lr] = bv.y; Bs[lk+2][lr] = bv.z; Bs[lk+3][lr] = bv.w;
        __syncthreads();
        #pragma unroll
        for (int kk = 0; kk < 8; kk++) {
            float4 a0 = *(const float4*)&As[kk][ty*8];
            float4 a1 = *(const float4*)&As[kk][ty*8+4];
            float4 b0 = *(const float4*)&Bs[kk][tx*8];
            float4 b1 = *(const float4*)&Bs[kk][tx*8+4];
            float a[8] = {a0.x,a0.y,a0.z,a0.w,a1.x,a1.y,a1.z,a1.w};
            float b[8] = {b0.x,b0.y,b0.z,b0.w,b1.x,b1.y,b1.z,b1.w};
            #pragma unroll
            for (int r = 0; r < 8; r++)
                #pragma unroll
                for (int s = 0; s < 8; s++) acc[r][s] += a[r]*b[s];
        }
    }
    #pragma unroll
    for (int r = 0; r < 8; r++) {
        int m = m0 + ty*8 + r;
        #pragma unroll
        for (int s = 0; s < 8; s++) {
            int n = n0 + tx*8 + s;
            if (n < N) {
                float v = acc[r][s];
                if (epi == 1) { v += bias[n]; v = v / (1.f + expf(-v)); }
                C[(size_t)m * N + n] = v;
            }
        }
    }
}

// ------------------------- front conv weight transpose -------------------------
__global__ void transpose_w(const float* __restrict__ w, float* __restrict__ wt, int KTAP)
{
    int idx = blockIdx.x * 256 + threadIdx.x;
    int total = 256 * 128 * KTAP;
    if (idx >= total) return;
    int o = idx & 255;
    int rest = idx >> 8;
    int i = rest & 127;
    int k = rest >> 7;
    wt[idx] = w[(size_t)o * 128 * KTAP + (size_t)i * KTAP + k];
}

// ------------------------- front conv -------------------------
template<int KTAP>
__global__ __launch_bounds__(256) void conv_front(
    const float* __restrict__ hmid, const float* __restrict__ wt,
    const float* __restrict__ bias, float* __restrict__ out, int colofs)
{
    const int PAD = KTAP / 2;
    __shared__ float As[16*64];
    __shared__ float Bs[16*64];
    int t0 = blockIdx.y * 64;
    int o0 = blockIdx.x * 64;
    int tid = threadIdx.x;
    int tx = tid & 15, ty = tid >> 4;
    float acc[4][4] = {};
    int tib0 = t0 & (TLEN - 1);
    for (int k = 0; k < KTAP; k++) {
        for (int kc = 0; kc < 8; kc++) {
            __syncthreads();
            #pragma unroll
            for (int e = tid; e < 1024; e += 256) {
                int ii = e & 15, tt = e >> 4;
                int ti = tib0 + tt + k - PAD;
                float v = 0.f;
                if (ti >= 0 && ti < TLEN)
                    v = hmid[(size_t)(t0 + tt + k - PAD) * 128 + kc*16 + ii];
                As[ii*64 + tt] = v;
            }
            #pragma unroll
            for (int e = tid; e < 1024; e += 256) {
                int oo = e & 63, ii = e >> 6;
                Bs[ii*64 + oo] = wt[(size_t)(k*128 + kc*16 + ii) * 256 + o0 + oo];
            }
            __syncthreads();
            #pragma unroll
            for (int ii = 0; ii < 16; ii++) {
                float4 a = *(const float4*)&As[ii*64 + ty*4];
                float4 b = *(const float4*)&Bs[ii*64 + tx*4];
                float av[4] = {a.x,a.y,a.z,a.w};
                float bv[4] = {b.x,b.y,b.z,b.w};
                #pragma unroll
                for (int r = 0; r < 4; r++)
                    #pragma unroll
                    for (int s = 0; s < 4; s++) acc[r][s] += av[r]*bv[s];
            }
        }
    }
    #pragma unroll
    for (int r = 0; r < 4; r++)
        #pragma unroll
        for (int s = 0; s < 4; s++) {
            int t = t0 + ty*4 + r, o = o0 + tx*4 + s;
            float v = acc[r][s] + bias[o];
            v = v / (1.f + expf(-v));
            out[(size_t)t * DMODEL + colofs + o] = v;
        }
}

// ------------------------- dt softplus -------------------------
__global__ void dt_softplus(const float* __restrict__ zx, const float* __restrict__ dtb,
                            float* __restrict__ dt)
{
    int idx = blockIdx.x * 256 + threadIdx.x;
    if (idx >= NTOK * NHEADS) return;
    int t = idx / NHEADS, hh = idx - t * NHEADS;
    float x = zx[(size_t)t * DINPROJ + 3200 + hh] + dtb[hh];
    dt[idx] = (x > 20.f) ? x : log1pf(expf(x));
}

// ------------------------- depthwise causal conv + silu -------------------------
__global__ void dwconv(const float* __restrict__ zx, const float* __restrict__ cw,
                       const float* __restrict__ cb, float* __restrict__ xBC)
{
    int c = blockIdx.x * 256 + threadIdx.x;
    int t = blockIdx.y;
    if (c >= CONVDIM) return;
    int ti = t & (TLEN - 1);
    float4 w = *(const float4*)(cw + (size_t)c * 4);
    float wk[4] = {w.x, w.y, w.z, w.w};
    float acc = cb[c];
    #pragma unroll
    for (int k = 0; k < 4; k++) {
        int tj = ti - 3 + k;
        if (tj >= 0) acc += zx[(size_t)(t - 3 + k) * DINPROJ + DINNER + c] * wk[k];
    }
    xBC[(size_t)t * CONVDIM + c] = acc / (1.f + expf(-acc));
}

// ------------------------- SSD per-chunk kernel -------------------------
__global__ __launch_bounds__(256) void ssd_chunk(
    const float* __restrict__ xBC, const float* __restrict__ dt,
    const float* __restrict__ A_log, const float* __restrict__ Dv,
    float* __restrict__ ys, float* __restrict__ Sg,
    float* __restrict__ segout, float* __restrict__ cdout)
{
    extern __shared__ float sm[];
    float* Bs  = sm;
    float* Cs  = Bs + 64*SMP;
    float* Ds  = Cs + 64*SMP;
    float* seg = Ds + 64*SMP;
    float* dec = seg + 64;
    float* dts = dec + 64;

    int blk = blockIdx.x;
    int h = blk % NHEADS;
    int c = (blk / NHEADS) & (NCHUNK - 1);
    int b = blk / (NHEADS * NCHUNK);
    int t0 = b * TLEN + c * 64;
    int tid = threadIdx.x;
    float A = -expf(A_log[h]);

    if (tid < 64) dts[tid] = dt[(size_t)(t0 + tid) * NHEADS + h];
    __syncthreads();
    for (int e = tid; e < 4096; e += 256) {
        int j = e >> 6, n = e & 63;
        const float* row = xBC + (size_t)(t0 + j) * CONVDIM;
        Bs[j*SMP + n] = row[DINNER + n];
        Cs[j*SMP + n] = row[DINNER + DSTATE + n];
        Ds[j*SMP + n] = dts[j] * row[h*64 + n];
    }
    if (tid < 64) seg[tid] = dts[tid] * A;
    __syncthreads();
    for (int off = 1; off < 64; off <<= 1) {
        float v = 0.f;
        bool act = (tid < 64) && (tid >= off);
        if (act) v = seg[tid - off];
        __syncthreads();
        if (act) seg[tid] += v;
        __syncthreads();
    }
    if (tid < 64) {
        dec[tid] = expf(seg[63] - seg[tid]);
        segout[(size_t)blk * 64 + tid] = seg[tid];
    }
    if (tid == 0) cdout[blk] = expf(seg[63]);
    __syncthreads();

    int tx = tid & 15, ty = tid >> 4;
    float acc[4][4] = {};
    #pragma unroll 4
    for (int n = 0; n < 64; n++) {
        float a[4], bb[4];
        #pragma unroll
        for (int r = 0; r < 4; r++) a[r] = Cs[(ty*4 + r)*SMP + n];
        #pragma unroll
        for (int s = 0; s < 4; s++) bb[s] = Bs[(tx*4 + s)*SMP + n];
        #pragma unroll
        for (int r = 0; r < 4; r++)
            #pragma unroll
            for (int s = 0; s < 4; s++) acc[r][s] += a[r]*bb[s];
    }
    __syncthreads();
    #pragma unroll
    for (int r = 0; r < 4; r++)
        #pragma unroll
        for (int s = 0; s < 4; s++) {
            int i = ty*4 + r, j = tx*4 + s;
            float v = 0.f;
            if (i >= j) v = expf(seg[i] - seg[j]) * acc[r][s];
            Cs[i*SMP + j] = v;
        }
    __syncthreads();
    float acc2[4][4] = {};
    #pragma unroll 4
    for (int j = 0; j < 64; j++) {
        float a[4], bb[4];
        #pragma unroll
        for (int r = 0; r < 4; r++) a[r] = Cs[(ty*4 + r)*SMP + j];
        #pragma unroll
        for (int s = 0; s < 4; s++) bb[s] = Ds[j*SMP + tx*4 + s];
        #pragma unroll
        for (int r = 0; r < 4; r++)
            #pragma unroll
            for (int s = 0; s < 4; s++) acc2[r][s] += a[r]*bb[s];
    }
    float Dh = Dv[h];
    #pragma unroll
    for (int r = 0; r < 4; r++)
        #pragma unroll
        for (int s = 0; s < 4; s++) {
            int i = t0 + ty*4 + r;
            int p = tx*4 + s;
            ys[(size_t)i * DINNER + h*64 + p] =
                acc2[r][s] + Dh * xBC[(size_t)i * CONVDIM + h*64 + p];
        }
    float acc3[4][4] = {};
    #pragma unroll 4
    for (int j = 0; j < 64; j++) {
        float dj = dec[j];
        float a[4], bb[4];
        #pragma unroll
        for (int r = 0; r < 4; r++) a[r] = Ds[j*SMP + ty*4 + r] * dj;
        #pragma unroll
        for (int s = 0; s < 4; s++) bb[s] = Bs[j*SMP + tx*4 + s];
        #pragma unroll
        for (int r = 0; r < 4; r++)
            #pragma unroll
            for (int s = 0; s < 4; s++) acc3[r][s] += a[r]*bb[s];
    }
    #pragma unroll
    for (int r = 0; r < 4; r++)
        #pragma unroll
        for (int s = 0; s < 4; s++)
            Sg[(size_t)blk * 4096 + (ty*4 + r)*64 + tx*4 + s] = acc3[r][s];
}

// ------------------------- inter-chunk scan -------------------------
__global__ __launch_bounds__(256) void ssd_scan(float* __restrict__ Sg,
                                                const float* __restrict__ cd)
{
    int blk = blockIdx.x;
    int h = blk % NHEADS, b = blk / NHEADS;
    int tid = threadIdx.x;
    float st[16];
    #pragma unroll
    for (int r = 0; r < 16; r++) st[r] = 0.f;
    for (int c = 0; c < NCHUNK; c++) {
        int bidx = (b * NCHUNK + c) * NHEADS + h;
        size_t base = (size_t)bidx * 4096;
        float d = cd[bidx];
        #pragma unroll
        for (int r = 0; r < 16; r++) {
            int e = tid + r*256;
            float s_in = Sg[base + e];
            float prev = st[r];
            st[r] = prev * d + s_in;
            Sg[base + e] = prev;
        }
    }
}

// ------------------------- y_inter accumulation -------------------------
__global__ __launch_bounds__(256) void ssd_inter(
    const float* __restrict__ xBC, const float* __restrict__ Sg,
    const float* __restrict__ segin, float* __restrict__ ys)
{
    __shared__ float Cs[64*SMP];
    __shared__ float Hs[64*SMP];
    __shared__ float seg[64];
    int blk = blockIdx.x;
    int h = blk % NHEADS;
    int c = (blk / NHEADS) & (NCHUNK - 1);
    int b = blk / (NHEADS * NCHUNK);
    int t0 = b * TLEN + c * 64;
    int tid = threadIdx.x;
    for (int e = tid; e < 4096; e += 256) {
        int j = e >> 6, n = e & 63;
        Cs[j*SMP + n] = xBC[(size_t)(t0 + j) * CONVDIM + DINNER + DSTATE + n];
        Hs[j*SMP + n] = Sg[(size_t)blk * 4096 + j*64 + n];
    }
    if (tid < 64) seg[tid] = segin[(size_t)blk * 64 + tid];
    __syncthreads();
    int tx = tid & 15, ty = tid >> 4;
    float acc[4][4] = {};
    #pragma unroll 4
    for (int n = 0; n < 64; n++) {
        float a[4], bb[4];
        #pragma unroll
        for (int r = 0; r < 4; r++) a[r] = Cs[(ty*4 + r)*SMP + n];
        #pragma unroll
        for (int s = 0; s < 4; s++) bb[s] = Hs[(tx*4 + s)*SMP + n];
        #pragma unroll
        for (int r = 0; r < 4; r++)
            #pragma unroll
            for (int s = 0; s < 4; s++) acc[r][s] += a[r]*bb[s];
    }
    #pragma unroll
    for (int r = 0; r < 4; r++) {
        float ei = expf(seg[ty*4 + r]);
        #pragma unroll
        for (int s = 0; s < 4; s++) {
            size_t idx = (size_t)(t0 + ty*4 + r) * DINNER + h*64 + tx*4 + s;
            ys[idx] += acc[r][s] * ei;
        }
    }
}

// ------------------------- gating + RMSNorm -------------------------
__global__ __launch_bounds__(256) void gate_rms(
    const float* __restrict__ ys, const float* __restrict__ zx,
    const float* __restrict__ nw, float* __restrict__ yg)
{
    __shared__ float red[32];
    int t = blockIdx.x, tid = threadIdx.x;
    float v[6];
    float ss = 0.f;
    #pragma unroll
    for (int r = 0; r < 6; r++) {
        int i = tid + r*256;
        float z = zx[(size_t)t * DINPROJ + i];
        float val = ys[(size_t)t * DINNER + i] * (z / (1.f + expf(-z)));
        v[r] = val;
        ss += val*val;
    }
    ss = blockReduceSum(ss, red);
    float sc = rsqrtf(ss / (float)DINNER + 1e-5f);
    #pragma unroll
    for (int r = 0; r < 6; r++) {
        int i = tid + r*256;
        yg[(size_t)t * DINNER + i] = v[r] * sc * nw[i];
    }
}

// ------------------------- residual + layernorm -------------------------
__global__ __launch_bounds__(256) void resid_ln(
    const float* __restrict__ y2, float* __restrict__ hio,
    const float* __restrict__ w, const float* __restrict__ b)
{
    __shared__ float red[32];
    int t = blockIdx.x, tid = threadIdx.x;
    float v[3];
    float s = 0.f;
    #pragma unroll
    for (int r = 0; r < 3; r++) {
        int i = tid + r*256;
        v[r] = y2[(size_t)t * DMODEL + i] + hio[(size_t)t * DMODEL + i];
        s += v[r];
    }
    s = blockReduceSum(s, red);
    float mean = s / (float)DMODEL;
    float q = 0.f;
    #pragma unroll
    for (int r = 0; r < 3; r++) { v[r] -= mean; q += v[r]*v[r]; }
    q = blockReduceSum(q, red);
    float inv = rsqrtf(q / (float)DMODEL + 1e-5f);
    #pragma unroll
    for (int r = 0; r < 3; r++) {
        int i = tid + r*256;
        hio[(size_t)t * DMODEL + i] = v[r] * inv * w[i] + b[i];
    }
}

// ------------------------- final layernorm + logits -------------------------
__global__ __launch_bounds__(256) void head_kernel(
    const float* __restrict__ hin,
    const float* __restrict__ fw, const float* __restrict__ fb,
    const float* __restrict__ lw, const float* __restrict__ lb,
    float* __restrict__ out)
{
    __shared__ float red[32];
    __shared__ float buf[DMODEL];
    int t = blockIdx.x, tid = threadIdx.x;
    float v[3];
    float s = 0.f;
    #pragma unroll
    for (int r = 0; r < 3; r++) {
        int i = tid + r*256;
        v[r] = hin[(size_t)t * DMODEL + i];
        s += v[r];
    }
    s = blockReduceSum(s, red);
    float mean = s / (float)DMODEL;
    float q = 0.f;
    #pragma unroll
    for (int r = 0; r < 3; r++) { v[r] -= mean; q += v[r]*v[r]; }
    q = blockReduceSum(q, red);
    float inv = rsqrtf(q / (float)DMODEL + 1e-5f);
    #pragma unroll
    for (int r = 0; r < 3; r++) {
        int i = tid + r*256;
        buf[i] = v[r] * inv * fw[i] + fb[i];
    }
    __syncthreads();
    for (int cls = 0; cls < 10; cls++) {
        float p = 0.f;
        #pragma unroll
        for (int r = 0; r < 3; r++) {
            int i = tid + r*256;
            p += buf[i] * lw[(size_t)cls * DMODEL + i];
        }
        p = blockReduceSum(p, red);
        if (tid == 0) out[(size_t)t * 10 + cls] = p + lb[cls];
    }
}

// ------------------------- launch -------------------------
extern "C" void kernel_launch(void* const* d_in, const int* in_sizes, int n_in,
                              void* d_out, int out_size)
{
    const float* x       = (const float*)d_in[0];
    const float* pc_w    = (const float*)d_in[1];
    const float* pc_b    = (const float*)d_in[2];
    const float* c1_w    = (const float*)d_in[3];
    const float* c1_b    = (const float*)d_in[4];
    const float* c2_w    = (const float*)d_in[5];
    const float* c2_b    = (const float*)d_in[6];
    const float* c3_w    = (const float*)d_in[7];
    const float* c3_b    = (const float*)d_in[8];
    const float* in_proj = (const float*)d_in[9];
    const float* conv_w  = (const float*)d_in[10];
    const float* conv_b  = (const float*)d_in[11];
    const float* dt_bias = (const float*)d_in[12];
    const float* A_log   = (const float*)d_in[13];
    const float* Dvec    = (const float*)d_in[14];
    const float* norm_w  = (const float*)d_in[15];
    const float* out_proj= (const float*)d_in[16];
    const float* ln_w    = (const float*)d_in[17];
    const float* ln_b    = (const float*)d_in[18];
    const float* fn_w    = (const float*)d_in[19];
    const float* fn_b    = (const float*)d_in[20];
    const float* lo_w    = (const float*)d_in[21];
    const float* lo_b    = (const float*)d_in[22];
    float* out = (float*)d_out;

    float *hmid, *h, *zx, *xBC, *dtb, *ys, *yg, *y2, *S, *segb, *cdb, *wt;
    __nv_bfloat16 *ahi, *alo, *wih, *wil, *woh, *wol;
    cudaGetSymbolAddress((void**)&hmid, g_hmid);
    cudaGetSymbolAddress((void**)&h,    g_h);
    cudaGetSymbolAddress((void**)&zx,   g_zx);
    cudaGetSymbolAddress((void**)&xBC,  g_xBC);
    cudaGetSymbolAddress((void**)&dtb,  g_dt);
    cudaGetSymbolAddress((void**)&ys,   g_ys);
    cudaGetSymbolAddress((void**)&yg,   g_yg);
    cudaGetSymbolAddress((void**)&y2,   g_y2);
    cudaGetSymbolAddress((void**)&S,    g_S);
    cudaGetSymbolAddress((void**)&segb, g_seg);
    cudaGetSymbolAddress((void**)&cdb,  g_cd);
    cudaGetSymbolAddress((void**)&wt,   g_wt);
    cudaGetSymbolAddress((void**)&ahi,  g_ahi);
    cudaGetSymbolAddress((void**)&alo,  g_alo);
    cudaGetSymbolAddress((void**)&wih,  g_wih);
    cudaGetSymbolAddress((void**)&wil,  g_wil);
    cudaGetSymbolAddress((void**)&woh,  g_woh);
    cudaGetSymbolAddress((void**)&wol,  g_wol);

    const int SSD_SMEM = (3 * 64 * SMP + 3 * 64) * (int)sizeof(float);
    cudaFuncSetAttribute(ssd_chunk, cudaFuncAttributeMaxDynamicSharedMemorySize, SSD_SMEM);
    const int MG_SMEM = 2 * MG_STAGE;   // 81920
    cudaFuncSetAttribute(mma_gemm, cudaFuncAttributeMaxDynamicSharedMemorySize, MG_SMEM);

    // ---- front ----
    gemm128_nt<<<dim3(1, NTOK/128), 256>>>(x, pc_w, hmid, 128, 64, pc_b, 1);
    transpose_w<<<(256*128*3  + 255)/256, 256>>>(c1_w, wt,               3);
    transpose_w<<<(256*128*9  + 255)/256, 256>>>(c2_w, wt + 3*128*256,   9);
    transpose_w<<<(256*128*27 + 255)/256, 256>>>(c3_w, wt + 12*128*256, 27);
    conv_front<3> <<<dim3(4, NTOK/64), 256>>>(hmid, wt,               c1_b, h, 0);
    conv_front<9> <<<dim3(4, NTOK/64), 256>>>(hmid, wt + 3*128*256,   c2_b, h, 256);
    conv_front<27><<<dim3(4, NTOK/64), 256>>>(hmid, wt + 12*128*256,  c3_b, h, 512);

    // ---- weight bf16 splits (all layers, every call — deterministic) ----
    {
        int n4 = 4 * DINPROJ * DMODEL / 4;
        split_bf16<<<(n4 + 255)/256, 256>>>((const float4*)in_proj, wih, wil, n4);
        int m4 = 4 * DMODEL * DINNER / 4;
        split_bf16<<<(m4 + 255)/256, 256>>>((const float4*)out_proj, woh, wol, m4);
    }

    // ---- layers ----
    for (int l = 0; l < 4; l++) {
        {
            int n4 = NTOK * DMODEL / 4;
            split_bf16<<<(n4 + 255)/256, 256>>>((const float4*)h, ahi, alo, n4);
        }
        mma_gemm<<<dim3((DINPROJ + 127)/128, NTOK/128), 256, MG_SMEM>>>(
            ahi, alo,
            wih + (size_t)l * DINPROJ * DMODEL, wil + (size_t)l * DINPROJ * DMODEL,
            zx, DINPROJ, DMODEL);
        dt_softplus<<<(NTOK*NHEADS + 255)/256, 256>>>(zx, dt_bias + l*NHEADS, dtb);
        dwconv<<<dim3((CONVDIM + 255)/256, NTOK), 256>>>(
            zx, conv_w + (size_t)l * CONVDIM * 4, conv_b + (size_t)l * CONVDIM, xBC);
        ssd_chunk<<<NBLK_SSD, 256, SSD_SMEM>>>(
            xBC, dtb, A_log + l*NHEADS, Dvec + l*NHEADS, ys, S, segb, cdb);
        ssd_scan<<<8*NHEADS, 256>>>(S, cdb);
        ssd_inter<<<NBLK_SSD, 256>>>(xBC, S, segb, ys);
        gate_rms<<<NTOK, 256>>>(ys, zx, norm_w + (size_t)l * DINNER, yg);
        {
            int n4 = NTOK * DINNER / 4;
            split_bf16<<<(n4 + 255)/256, 256>>>((const float4*)yg, ahi, alo, n4);
        }
        mma_gemm<<<dim3(DMODEL/128, NTOK/128), 256, MG_SMEM>>>(
            ahi, alo,
            woh + (size_t)l * DMODEL * DINNER, wol + (size_t)l * DMODEL * DINNER,
            y2, DMODEL, DINNER);
        resid_ln<<<NTOK, 256>>>(y2, h, ln_w + (size_t)l * DMODEL, ln_b + (size_t)l * DMODEL);
    }

    // ---- head ----
    head_kernel<<<NTOK, 256>>>(h, fn_w, fn_b, lo_w, lo_b, out);
    (void)in_sizes; (void)n_in; (void)out_size;
}

// round 5
// speedup vs baseline: 1.7620x; 1.0093x over previous
#include <cuda_runtime.h>
#include <cuda_bf16.h>
#include <cstdint>
#include <math.h>

#define NTOK   16384
#define TLEN   2048
#define DMODEL 768
#define DINNER 1536
#define DSTATE 64
#define NHEADS 24
#define CONVDIM 1664
#define DINPROJ 3224
#define NCHUNK 32
#define NBLK_SSD (8*NCHUNK*NHEADS)   /* 6144 */
#define SMP 65

// ------------------------- scratch (device globals) -------------------------
__device__ float g_hmid[(size_t)NTOK*128];
__device__ float g_h   [(size_t)NTOK*DMODEL];
__device__ float g_zx  [(size_t)NTOK*DINPROJ];
__device__ float g_xBC [(size_t)NTOK*CONVDIM];
__device__ float g_dt  [(size_t)NTOK*NHEADS];
__device__ float g_ys  [(size_t)NTOK*DINNER];
__device__ float g_y2  [(size_t)NTOK*DMODEL];
__device__ float g_S   [(size_t)NBLK_SSD*4096];
__device__ float g_seg [(size_t)NBLK_SSD*64];
__device__ float g_cd  [NBLK_SSD];
__device__ float g_wt  [(size_t)(3+9+27)*128*256];
// bf16 split buffers (A operand: doubles as h-split and yg-split)
__device__ __nv_bfloat16 g_ahi[(size_t)NTOK*DINNER];
__device__ __nv_bfloat16 g_alo[(size_t)NTOK*DINNER];
__device__ __nv_bfloat16 g_wih[(size_t)4*DINPROJ*DMODEL];
__device__ __nv_bfloat16 g_wil[(size_t)4*DINPROJ*DMODEL];
__device__ __nv_bfloat16 g_woh[(size_t)4*DMODEL*DINNER];
__device__ __nv_bfloat16 g_wol[(size_t)4*DMODEL*DINNER];

// ------------------------- PTX helpers -------------------------
__device__ __forceinline__ uint32_t smem_u32(const void* p) {
    uint32_t a;
    asm("{ .reg .u64 t; cvta.to.shared.u64 t, %1; cvt.u32.u64 %0, t; }" : "=r"(a) : "l"(p));
    return a;
}
__device__ __forceinline__ void cp16z(uint32_t dst, const void* src, int srcsz) {
    asm volatile("cp.async.cg.shared.global [%0], [%1], 16, %2;" :: "r"(dst), "l"(src), "r"(srcsz));
}
__device__ __forceinline__ void ldsm4(uint32_t* r, uint32_t addr) {
    asm volatile("ldmatrix.sync.aligned.m8n8.x4.shared.b16 {%0,%1,%2,%3}, [%4];"
        : "=r"(r[0]), "=r"(r[1]), "=r"(r[2]), "=r"(r[3]) : "r"(addr));
}
__device__ __forceinline__ void mma16816(float* c, const uint32_t* a, const uint32_t* b) {
    asm volatile("mma.sync.aligned.m16n8k16.row.col.f32.bf16.bf16.f32 "
        "{%0,%1,%2,%3}, {%4,%5,%6,%7}, {%8,%9}, {%0,%1,%2,%3};"
        : "+f"(c[0]), "+f"(c[1]), "+f"(c[2]), "+f"(c[3])
        : "r"(a[0]), "r"(a[1]), "r"(a[2]), "r"(a[3]), "r"(b[0]), "r"(b[1]));
}
__device__ __forceinline__ void split1(float v, __nv_bfloat16& hi, __nv_bfloat16& lo) {
    hi = __float2bfloat16(v);
    lo = __float2bfloat16(v - __bfloat162float(hi));
}

// ------------------------- split fp32 -> bf16 hi/lo (weights) -------------------------
__global__ void split_bf16(const float4* __restrict__ src,
                           __nv_bfloat16* __restrict__ hi,
                           __nv_bfloat16* __restrict__ lo, int n4)
{
    int i = blockIdx.x * 256 + threadIdx.x;
    if (i >= n4) return;
    float4 v = src[i];
    float vv[4] = {v.x, v.y, v.z, v.w};
    __nv_bfloat16 h4[4], l4[4];
    #pragma unroll
    for (int j = 0; j < 4; j++) split1(vv[j], h4[j], l4[j]);
    uint2 hp, lp;
    hp.x = (uint32_t)*(uint16_t*)&h4[0] | ((uint32_t)*(uint16_t*)&h4[1] << 16);
    hp.y = (uint32_t)*(uint16_t*)&h4[2] | ((uint32_t)*(uint16_t*)&h4[3] << 16);
    lp.x = (uint32_t)*(uint16_t*)&l4[0] | ((uint32_t)*(uint16_t*)&l4[1] << 16);
    lp.y = (uint32_t)*(uint16_t*)&l4[2] | ((uint32_t)*(uint16_t*)&l4[3] << 16);
    *reinterpret_cast<uint2*>(hi + (size_t)i * 4) = hp;
    *reinterpret_cast<uint2*>(lo + (size_t)i * 4) = lp;
}

// ------------------------- mma.sync split-bf16 NT GEMM, 64x128 tile -------------------------
// C[M][N] = A[M][K] * B[N][K]^T (~fp32: AhBh + AhBl + AlBh).
// M mult of 64, N mult of 8, K mult of 32. 128 threads, 3 CTAs/SM.
#define MG_PITCH 80
#define MG_AMAT  5120             /* 64*80 */
#define MG_BBASE 10240            /* after Ah,Al */
#define MG_BMAT  10240            /* 128*80 */
#define MG_STAGE 30720

__device__ __forceinline__ void mg_load(
    uint32_t sbase,
    const __nv_bfloat16* __restrict__ Ah, const __nv_bfloat16* __restrict__ Al,
    const __nv_bfloat16* __restrict__ Bh, const __nv_bfloat16* __restrict__ Bl,
    int m0, int n0, int Ntot, int K, int c, int tid)
{
    // A: 2 mats x 64 rows x 4 segs = 512 cp16
    #pragma unroll
    for (int j = 0; j < 4; j++) {
        int e = tid + j * 128;
        int seg = e & 3, r = (e >> 2) & 63, mat = e >> 8;
        uint32_t soff = (uint32_t)(mat * MG_AMAT + r * MG_PITCH + seg * 16);
        const __nv_bfloat16* src = (mat ? Al : Ah) + (size_t)(m0 + r) * K + (size_t)c * 32 + seg * 8;
        cp16z(sbase + soff, src, 16);
    }
    // B: 2 mats x 128 rows x 4 segs = 1024 cp16
    #pragma unroll
    for (int j = 0; j < 8; j++) {
        int e = tid + j * 128;
        int seg = e & 3, r = (e >> 2) & 127, mat = e >> 9;
        uint32_t soff = (uint32_t)(MG_BBASE + mat * MG_BMAT + r * MG_PITCH + seg * 16);
        int nr = n0 + r;
        int sz = (nr < Ntot) ? 16 : 0;
        int nrc = (nr < Ntot) ? nr : 0;
        const __nv_bfloat16* src = (mat ? Bl : Bh) + (size_t)nrc * K + (size_t)c * 32 + seg * 8;
        cp16z(sbase + soff, src, sz);
    }
    asm volatile("cp.async.commit_group;" ::: "memory");
}

__global__ __launch_bounds__(128, 3) void mma_gemm(
    const __nv_bfloat16* __restrict__ Ah, const __nv_bfloat16* __restrict__ Al,
    const __nv_bfloat16* __restrict__ Bh, const __nv_bfloat16* __restrict__ Bl,
    float* __restrict__ C, int Ntot, int K)
{
    extern __shared__ char smem[];
    uint32_t sb = smem_u32(smem);
    int tid = threadIdx.x, wid = tid >> 5, lane = tid & 31;
    int m0 = blockIdx.y * 64, n0 = blockIdx.x * 128;
    int wm = (wid >> 1) * 32;      // warp m offset (0/32)
    int wn = (wid & 1) * 64;       // warp n offset (0/64)

    float acc[2][8][4];
    #pragma unroll
    for (int a = 0; a < 2; a++)
        #pragma unroll
        for (int b = 0; b < 8; b++)
            #pragma unroll
            for (int q = 0; q < 4; q++) acc[a][b][q] = 0.f;

    int gr = lane >> 3, lr = lane & 7;
    int arow = (gr & 1) * 8 + lr;
    int acol = (gr >> 1) * 16;
    int brow = (gr >> 1) * 8 + lr;
    int bcol = (gr & 1) * 16;

    int nch = K >> 5;
    mg_load(sb, Ah, Al, Bh, Bl, m0, n0, Ntot, K, 0, tid);
    for (int c = 0; c < nch; c++) {
        if (c + 1 < nch) {
            mg_load(sb + ((c + 1) & 1) * MG_STAGE, Ah, Al, Bh, Bl, m0, n0, Ntot, K, c + 1, tid);
            asm volatile("cp.async.wait_group 1;" ::: "memory");
        } else {
            asm volatile("cp.async.wait_group 0;" ::: "memory");
        }
        __syncthreads();
        uint32_t base = sb + (uint32_t)(c & 1) * MG_STAGE;
        #pragma unroll
        for (int ks = 0; ks < 2; ks++) {
            uint32_t ah[2][4], al[2][4];
            #pragma unroll
            for (int mt = 0; mt < 2; mt++) {
                uint32_t off = (uint32_t)((wm + mt*16 + arow) * MG_PITCH + acol + ks*32);
                ldsm4(ah[mt], base + off);
                ldsm4(al[mt], base + MG_AMAT + off);
            }
            uint32_t bh[4][4], bl[4][4];
            #pragma unroll
            for (int np = 0; np < 4; np++) {
                uint32_t off = (uint32_t)(MG_BBASE + (wn + np*16 + brow) * MG_PITCH + bcol + ks*32);
                ldsm4(bh[np], base + off);
                ldsm4(bl[np], base + MG_BMAT + off);
            }
            #pragma unroll
            for (int mt = 0; mt < 2; mt++)
                #pragma unroll
                for (int np = 0; np < 4; np++) {
                    mma16816(acc[mt][2*np],   ah[mt], &bh[np][0]);
                    mma16816(acc[mt][2*np+1], ah[mt], &bh[np][2]);
                    mma16816(acc[mt][2*np],   ah[mt], &bl[np][0]);
                    mma16816(acc[mt][2*np+1], ah[mt], &bl[np][2]);
                    mma16816(acc[mt][2*np],   al[mt], &bh[np][0]);
                    mma16816(acc[mt][2*np+1], al[mt], &bh[np][2]);
                }
        }
        __syncthreads();
    }

    int r4 = lane >> 2, c2 = (lane & 3) * 2;
    #pragma unroll
    for (int mt = 0; mt < 2; mt++) {
        int r = m0 + wm + mt*16 + r4;
        #pragma unroll
        for (int nt = 0; nt < 8; nt++) {
            int col = n0 + wn + nt*8 + c2;
            if (col < Ntot) {
                float* cc = acc[mt][nt];
                *(float2*)&C[(size_t)r * Ntot + col]       = make_float2(cc[0], cc[1]);
                *(float2*)&C[(size_t)(r + 8) * Ntot + col] = make_float2(cc[2], cc[3]);
            }
        }
    }
}

// ------------------------- helpers -------------------------
__device__ __forceinline__ float blockReduceSum(float v, float* red) {
    int tid = threadIdx.x;
    #pragma unroll
    for (int o = 16; o; o >>= 1) v += __shfl_xor_sync(0xffffffffu, v, o);
    if ((tid & 31) == 0) red[tid >> 5] = v;
    __syncthreads();
    if (tid < 32) {
        float w = (tid < 8) ? red[tid] : 0.f;
        #pragma unroll
        for (int o = 4; o; o >>= 1) w += __shfl_xor_sync(0xffffffffu, w, o);
        if (tid == 0) red[0] = w;
    }
    __syncthreads();
    float r0 = red[0];
    __syncthreads();
    return r0;
}

// ------------------------- small fp32 NT SGEMM (front 1x1) -------------------------
__global__ __launch_bounds__(256) void gemm128_nt(
    const float* __restrict__ A, const float* __restrict__ B,
    float* __restrict__ C, int N, int K,
    const float* __restrict__ bias, int epi)
{
    __shared__ float As[8][128];
    __shared__ float Bs[8][128];
    int m0 = blockIdx.y * 128, n0 = blockIdx.x * 128;
    int tid = threadIdx.x;
    int tx = tid & 15, ty = tid >> 4;
    float acc[8][8] = {};
    int lr = tid >> 1;
    int lk = (tid & 1) * 4;
    const float* Ag = A + (size_t)(m0 + lr) * K + lk;
    const float* Bg = B + (size_t)(n0 + lr) * K + lk;
    bool bvalid = (n0 + lr) < N;
    for (int k0 = 0; k0 < K; k0 += 8) {
        float4 av = *(const float4*)(Ag + k0);
        float4 bv = bvalid ? *(const float4*)(Bg + k0) : make_float4(0.f,0.f,0.f,0.f);
        __syncthreads();
        As[lk+0][lr] = av.x; As[lk+1][lr] = av.y; As[lk+2][lr] = av.z; As[lk+3][lr] = av.w;
        Bs[lk+0][lr] = bv.x; Bs[lk+1][lr] = bv.y; Bs[lk+2][lr] = bv.z; Bs[lk+3][lr] = bv.w;
        __syncthreads();
        #pragma unroll
        for (int kk = 0; kk < 8; kk++) {
            float4 a0 = *(const float4*)&As[kk][ty*8];
            float4 a1 = *(const float4*)&As[kk][ty*8+4];
            float4 b0 = *(const float4*)&Bs[kk][tx*8];
            float4 b1 = *(const float4*)&Bs[kk][tx*8+4];
            float a[8] = {a0.x,a0.y,a0.z,a0.w,a1.x,a1.y,a1.z,a1.w};
            float b[8] = {b0.x,b0.y,b0.z,b0.w,b1.x,b1.y,b1.z,b1.w};
            #pragma unroll
            for (int r = 0; r < 8; r++)
                #pragma unroll
                for (int s = 0; s < 8; s++) acc[r][s] += a[r]*b[s];
        }
    }
    #pragma unroll
    for (int r = 0; r < 8; r++) {
        int m = m0 + ty*8 + r;
        #pragma unroll
        for (int s = 0; s < 8; s++) {
            int n = n0 + tx*8 + s;
            if (n < N) {
                float v = acc[r][s];
                if (epi == 1) { v += bias[n]; v = v / (1.f + expf(-v)); }
                C[(size_t)m * N + n] = v;
            }
        }
    }
}

// ------------------------- front conv weight transpose -------------------------
__global__ void transpose_w(const float* __restrict__ w, float* __restrict__ wt, int KTAP)
{
    int idx = blockIdx.x * 256 + threadIdx.x;
    int total = 256 * 128 * KTAP;
    if (idx >= total) return;
    int o = idx & 255;
    int rest = idx >> 8;
    int i = rest & 127;
    int k = rest >> 7;
    wt[idx] = w[(size_t)o * 128 * KTAP + (size_t)i * KTAP + k];
}

// ------------------------- front conv (writes h + bf16 split) -------------------------
template<int KTAP>
__global__ __launch_bounds__(256) void conv_front(
    const float* __restrict__ hmid, const float* __restrict__ wt,
    const float* __restrict__ bias, float* __restrict__ out,
    __nv_bfloat16* __restrict__ ohi, __nv_bfloat16* __restrict__ olo, int colofs)
{
    const int PAD = KTAP / 2;
    __shared__ float As[16*64];
    __shared__ float Bs[16*64];
    int t0 = blockIdx.y * 64;
    int o0 = blockIdx.x * 64;
    int tid = threadIdx.x;
    int tx = tid & 15, ty = tid >> 4;
    float acc[4][4] = {};
    int tib0 = t0 & (TLEN - 1);
    for (int k = 0; k < KTAP; k++) {
        for (int kc = 0; kc < 8; kc++) {
            __syncthreads();
            #pragma unroll
            for (int e = tid; e < 1024; e += 256) {
                int ii = e & 15, tt = e >> 4;
                int ti = tib0 + tt + k - PAD;
                float v = 0.f;
                if (ti >= 0 && ti < TLEN)
                    v = hmid[(size_t)(t0 + tt + k - PAD) * 128 + kc*16 + ii];
                As[ii*64 + tt] = v;
            }
            #pragma unroll
            for (int e = tid; e < 1024; e += 256) {
                int oo = e & 63, ii = e >> 6;
                Bs[ii*64 + oo] = wt[(size_t)(k*128 + kc*16 + ii) * 256 + o0 + oo];
            }
            __syncthreads();
            #pragma unroll
            for (int ii = 0; ii < 16; ii++) {
                float4 a = *(const float4*)&As[ii*64 + ty*4];
                float4 b = *(const float4*)&Bs[ii*64 + tx*4];
                float av[4] = {a.x,a.y,a.z,a.w};
                float bv[4] = {b.x,b.y,b.z,b.w};
                #pragma unroll
                for (int r = 0; r < 4; r++)
                    #pragma unroll
                    for (int s = 0; s < 4; s++) acc[r][s] += av[r]*bv[s];
            }
        }
    }
    #pragma unroll
    for (int r = 0; r < 4; r++)
        #pragma unroll
        for (int s = 0; s < 4; s++) {
            int t = t0 + ty*4 + r, o = o0 + tx*4 + s;
            float v = acc[r][s] + bias[o];
            v = v / (1.f + expf(-v));
            size_t idx = (size_t)t * DMODEL + colofs + o;
            out[idx] = v;
            __nv_bfloat16 hi, lo;
            split1(v, hi, lo);
            ohi[idx] = hi;
            olo[idx] = lo;
        }
}

// ------------------------- dt softplus -------------------------
__global__ void dt_softplus(const float* __restrict__ zx, const float* __restrict__ dtb,
                            float* __restrict__ dt)
{
    int idx = blockIdx.x * 256 + threadIdx.x;
    if (idx >= NTOK * NHEADS) return;
    int t = idx / NHEADS, hh = idx - t * NHEADS;
    float x = zx[(size_t)t * DINPROJ + 3200 + hh] + dtb[hh];
    dt[idx] = (x > 20.f) ? x : log1pf(expf(x));
}

// ------------------------- depthwise causal conv + silu -------------------------
__global__ void dwconv(const float* __restrict__ zx, const float* __restrict__ cw,
                       const float* __restrict__ cb, float* __restrict__ xBC)
{
    int c = blockIdx.x * 256 + threadIdx.x;
    int t = blockIdx.y;
    if (c >= CONVDIM) return;
    int ti = t & (TLEN - 1);
    float4 w = *(const float4*)(cw + (size_t)c * 4);
    float wk[4] = {w.x, w.y, w.z, w.w};
    float acc = cb[c];
    #pragma unroll
    for (int k = 0; k < 4; k++) {
        int tj = ti - 3 + k;
        if (tj >= 0) acc += zx[(size_t)(t - 3 + k) * DINPROJ + DINNER + c] * wk[k];
    }
    xBC[(size_t)t * CONVDIM + c] = acc / (1.f + expf(-acc));
}

// ------------------------- SSD per-chunk kernel -------------------------
__global__ __launch_bounds__(256) void ssd_chunk(
    const float* __restrict__ xBC, const float* __restrict__ dt,
    const float* __restrict__ A_log, const float* __restrict__ Dv,
    float* __restrict__ ys, float* __restrict__ Sg,
    float* __restrict__ segout, float* __restrict__ cdout)
{
    extern __shared__ float sm[];
    float* Bs  = sm;
    float* Cs  = Bs + 64*SMP;
    float* Ds  = Cs + 64*SMP;
    float* seg = Ds + 64*SMP;
    float* dec = seg + 64;
    float* dts = dec + 64;

    int blk = blockIdx.x;
    int h = blk % NHEADS;
    int c = (blk / NHEADS) & (NCHUNK - 1);
    int b = blk / (NHEADS * NCHUNK);
    int t0 = b * TLEN + c * 64;
    int tid = threadIdx.x;
    float A = -expf(A_log[h]);

    if (tid < 64) dts[tid] = dt[(size_t)(t0 + tid) * NHEADS + h];
    __syncthreads();
    for (int e = tid; e < 4096; e += 256) {
        int j = e >> 6, n = e & 63;
        const float* row = xBC + (size_t)(t0 + j) * CONVDIM;
        Bs[j*SMP + n] = row[DINNER + n];
        Cs[j*SMP + n] = row[DINNER + DSTATE + n];
        Ds[j*SMP + n] = dts[j] * row[h*64 + n];
    }
    if (tid < 64) seg[tid] = dts[tid] * A;
    __syncthreads();
    for (int off = 1; off < 64; off <<= 1) {
        float v = 0.f;
        bool act = (tid < 64) && (tid >= off);
        if (act) v = seg[tid - off];
        __syncthreads();
        if (act) seg[tid] += v;
        __syncthreads();
    }
    if (tid < 64) {
        dec[tid] = expf(seg[63] - seg[tid]);
        segout[(size_t)blk * 64 + tid] = seg[tid];
    }
    if (tid == 0) cdout[blk] = expf(seg[63]);
    __syncthreads();

    int tx = tid & 15, ty = tid >> 4;
    float acc[4][4] = {};
    #pragma unroll 4
    for (int n = 0; n < 64; n++) {
        float a[4], bb[4];
        #pragma unroll
        for (int r = 0; r < 4; r++) a[r] = Cs[(ty*4 + r)*SMP + n];
        #pragma unroll
        for (int s = 0; s < 4; s++) bb[s] = Bs[(tx*4 + s)*SMP + n];
        #pragma unroll
        for (int r = 0; r < 4; r++)
            #pragma unroll
            for (int s = 0; s < 4; s++) acc[r][s] += a[r]*bb[s];
    }
    __syncthreads();
    #pragma unroll
    for (int r = 0; r < 4; r++)
        #pragma unroll
        for (int s = 0; s < 4; s++) {
            int i = ty*4 + r, j = tx*4 + s;
            float v = 0.f;
            if (i >= j) v = expf(seg[i] - seg[j]) * acc[r][s];
            Cs[i*SMP + j] = v;
        }
    __syncthreads();
    float acc2[4][4] = {};
    #pragma unroll 4
    for (int j = 0; j < 64; j++) {
        float a[4], bb[4];
        #pragma unroll
        for (int r = 0; r < 4; r++) a[r] = Cs[(ty*4 + r)*SMP + j];
        #pragma unroll
        for (int s = 0; s < 4; s++) bb[s] = Ds[j*SMP + tx*4 + s];
        #pragma unroll
        for (int r = 0; r < 4; r++)
            #pragma unroll
            for (int s = 0; s < 4; s++) acc2[r][s] += a[r]*bb[s];
    }
    float Dh = Dv[h];
    #pragma unroll
    for (int r = 0; r < 4; r++)
        #pragma unroll
        for (int s = 0; s < 4; s++) {
            int i = t0 + ty*4 + r;
            int p = tx*4 + s;
            ys[(size_t)i * DINNER + h*64 + p] =
                acc2[r][s] + Dh * xBC[(size_t)i * CONVDIM + h*64 + p];
        }
    float acc3[4][4] = {};
    #pragma unroll 4
    for (int j = 0; j < 64; j++) {
        float dj = dec[j];
        float a[4], bb[4];
        #pragma unroll
        for (int r = 0; r < 4; r++) a[r] = Ds[j*SMP + ty*4 + r] * dj;
        #pragma unroll
        for (int s = 0; s < 4; s++) bb[s] = Bs[j*SMP + tx*4 + s];
        #pragma unroll
        for (int r = 0; r < 4; r++)
            #pragma unroll
            for (int s = 0; s < 4; s++) acc3[r][s] += a[r]*bb[s];
    }
    #pragma unroll
    for (int r = 0; r < 4; r++)
        #pragma unroll
        for (int s = 0; s < 4; s++)
            Sg[(size_t)blk * 4096 + (ty*4 + r)*64 + tx*4 + s] = acc3[r][s];
}

// ------------------------- inter-chunk scan -------------------------
__global__ __launch_bounds__(256) void ssd_scan(float* __restrict__ Sg,
                                                const float* __restrict__ cd)
{
    int blk = blockIdx.x;
    int h = blk % NHEADS, b = blk / NHEADS;
    int tid = threadIdx.x;
    float st[16];
    #pragma unroll
    for (int r = 0; r < 16; r++) st[r] = 0.f;
    for (int c = 0; c < NCHUNK; c++) {
        int bidx = (b * NCHUNK + c) * NHEADS + h;
        size_t base = (size_t)bidx * 4096;
        float d = cd[bidx];
        #pragma unroll
        for (int r = 0; r < 16; r++) {
            int e = tid + r*256;
            float s_in = Sg[base + e];
            float prev = st[r];
            st[r] = prev * d + s_in;
            Sg[base + e] = prev;
        }
    }
}

// ------------------------- y_inter accumulation -------------------------
__global__ __launch_bounds__(256) void ssd_inter(
    const float* __restrict__ xBC, const float* __restrict__ Sg,
    const float* __restrict__ segin, float* __restrict__ ys)
{
    __shared__ float Cs[64*SMP];
    __shared__ float Hs[64*SMP];
    __shared__ float seg[64];
    int blk = blockIdx.x;
    int h = blk % NHEADS;
    int c = (blk / NHEADS) & (NCHUNK - 1);
    int b = blk / (NHEADS * NCHUNK);
    int t0 = b * TLEN + c * 64;
    int tid = threadIdx.x;
    for (int e = tid; e < 4096; e += 256) {
        int j = e >> 6, n = e & 63;
        Cs[j*SMP + n] = xBC[(size_t)(t0 + j) * CONVDIM + DINNER + DSTATE + n];
        Hs[j*SMP + n] = Sg[(size_t)blk * 4096 + j*64 + n];
    }
    if (tid < 64) seg[tid] = segin[(size_t)blk * 64 + tid];
    __syncthreads();
    int tx = tid & 15, ty = tid >> 4;
    float acc[4][4] = {};
    #pragma unroll 4
    for (int n = 0; n < 64; n++) {
        float a[4], bb[4];
        #pragma unroll
        for (int r = 0; r < 4; r++) a[r] = Cs[(ty*4 + r)*SMP + n];
        #pragma unroll
        for (int s = 0; s < 4; s++) bb[s] = Hs[(tx*4 + s)*SMP + n];
        #pragma unroll
        for (int r = 0; r < 4; r++)
            #pragma unroll
            for (int s = 0; s < 4; s++) acc[r][s] += a[r]*bb[s];
    }
    #pragma unroll
    for (int r = 0; r < 4; r++) {
        float ei = expf(seg[ty*4 + r]);
        #pragma unroll
        for (int s = 0; s < 4; s++) {
            size_t idx = (size_t)(t0 + ty*4 + r) * DINNER + h*64 + tx*4 + s;
            ys[idx] += acc[r][s] * ei;
        }
    }
}

// ------------------------- gating + RMSNorm (writes bf16 split directly) -------------------------
__global__ __launch_bounds__(256) void gate_rms(
    const float* __restrict__ ys, const float* __restrict__ zx,
    const float* __restrict__ nw,
    __nv_bfloat16* __restrict__ ohi, __nv_bfloat16* __restrict__ olo)
{
    __shared__ float red[32];
    int t = blockIdx.x, tid = threadIdx.x;
    float v[6];
    float ss = 0.f;
    #pragma unroll
    for (int r = 0; r < 6; r++) {
        int i = tid + r*256;
        float z = zx[(size_t)t * DINPROJ + i];
        float val = ys[(size_t)t * DINNER + i] * (z / (1.f + expf(-z)));
        v[r] = val;
        ss += val*val;
    }
    ss = blockReduceSum(ss, red);
    float sc = rsqrtf(ss / (float)DINNER + 1e-5f);
    #pragma unroll
    for (int r = 0; r < 6; r++) {
        int i = tid + r*256;
        float val = v[r] * sc * nw[i];
        __nv_bfloat16 hi, lo;
        split1(val, hi, lo);
        size_t idx = (size_t)t * DINNER + i;
        ohi[idx] = hi;
        olo[idx] = lo;
    }
}

// ------------------------- residual + layernorm (writes h + bf16 split) -------------------------
__global__ __launch_bounds__(256) void resid_ln(
    const float* __restrict__ y2, float* __restrict__ hio,
    const float* __restrict__ w, const float* __restrict__ b,
    __nv_bfloat16* __restrict__ ohi, __nv_bfloat16* __restrict__ olo)
{
    __shared__ float red[32];
    int t = blockIdx.x, tid = threadIdx.x;
    float v[3];
    float s = 0.f;
    #pragma unroll
    for (int r = 0; r < 3; r++) {
        int i = tid + r*256;
        v[r] = y2[(size_t)t * DMODEL + i] + hio[(size_t)t * DMODEL + i];
        s += v[r];
    }
    s = blockReduceSum(s, red);
    float mean = s / (float)DMODEL;
    float q = 0.f;
    #pragma unroll
    for (int r = 0; r < 3; r++) { v[r] -= mean; q += v[r]*v[r]; }
    q = blockReduceSum(q, red);
    float inv = rsqrtf(q / (float)DMODEL + 1e-5f);
    #pragma unroll
    for (int r = 0; r < 3; r++) {
        int i = tid + r*256;
        float val = v[r] * inv * w[i] + b[i];
        size_t idx = (size_t)t * DMODEL + i;
        hio[idx] = val;
        __nv_bfloat16 hi, lo;
        split1(val, hi, lo);
        ohi[idx] = hi;
        olo[idx] = lo;
    }
}

// ------------------------- final layernorm + logits -------------------------
__global__ __launch_bounds__(256) void head_kernel(
    const float* __restrict__ hin,
    const float* __restrict__ fw, const float* __restrict__ fb,
    const float* __restrict__ lw, const float* __restrict__ lb,
    float* __restrict__ out)
{
    __shared__ float red[32];
    __shared__ float buf[DMODEL];
    int t = blockIdx.x, tid = threadIdx.x;
    float v[3];
    float s = 0.f;
    #pragma unroll
    for (int r = 0; r < 3; r++) {
        int i = tid + r*256;
        v[r] = hin[(size_t)t * DMODEL + i];
        s += v[r];
    }
    s = blockReduceSum(s, red);
    float mean = s / (float)DMODEL;
    float q = 0.f;
    #pragma unroll
    for (int r = 0; r < 3; r++) { v[r] -= mean; q += v[r]*v[r]; }
    q = blockReduceSum(q, red);
    float inv = rsqrtf(q / (float)DMODEL + 1e-5f);
    #pragma unroll
    for (int r = 0; r < 3; r++) {
        int i = tid + r*256;
        buf[i] = v[r] * inv * fw[i] + fb[i];
    }
    __syncthreads();
    for (int cls = 0; cls < 10; cls++) {
        float p = 0.f;
        #pragma unroll
        for (int r = 0; r < 3; r++) {
            int i = tid + r*256;
            p += buf[i] * lw[(size_t)cls * DMODEL + i];
        }
        p = blockReduceSum(p, red);
        if (tid == 0) out[(size_t)t * 10 + cls] = p + lb[cls];
    }
}

// ------------------------- launch -------------------------
extern "C" void kernel_launch(void* const* d_in, const int* in_sizes, int n_in,
                              void* d_out, int out_size)
{
    const float* x       = (const float*)d_in[0];
    const float* pc_w    = (const float*)d_in[1];
    const float* pc_b    = (const float*)d_in[2];
    const float* c1_w    = (const float*)d_in[3];
    const float* c1_b    = (const float*)d_in[4];
    const float* c2_w    = (const float*)d_in[5];
    const float* c2_b    = (const float*)d_in[6];
    const float* c3_w    = (const float*)d_in[7];
    const float* c3_b    = (const float*)d_in[8];
    const float* in_proj = (const float*)d_in[9];
    const float* conv_w  = (const float*)d_in[10];
    const float* conv_b  = (const float*)d_in[11];
    const float* dt_bias = (const float*)d_in[12];
    const float* A_log   = (const float*)d_in[13];
    const float* Dvec    = (const float*)d_in[14];
    const float* norm_w  = (const float*)d_in[15];
    const float* out_proj= (const float*)d_in[16];
    const float* ln_w    = (const float*)d_in[17];
    const float* ln_b    = (const float*)d_in[18];
    const float* fn_w    = (const float*)d_in[19];
    const float* fn_b    = (const float*)d_in[20];
    const float* lo_w    = (const float*)d_in[21];
    const float* lo_b    = (const float*)d_in[22];
    float* out = (float*)d_out;

    float *hmid, *h, *zx, *xBC, *dtb, *ys, *y2, *S, *segb, *cdb, *wt;
    __nv_bfloat16 *ahi, *alo, *wih, *wil, *woh, *wol;
    cudaGetSymbolAddress((void**)&hmid, g_hmid);
    cudaGetSymbolAddress((void**)&h,    g_h);
    cudaGetSymbolAddress((void**)&zx,   g_zx);
    cudaGetSymbolAddress((void**)&xBC,  g_xBC);
    cudaGetSymbolAddress((void**)&dtb,  g_dt);
    cudaGetSymbolAddress((void**)&ys,   g_ys);
    cudaGetSymbolAddress((void**)&y2,   g_y2);
    cudaGetSymbolAddress((void**)&S,    g_S);
    cudaGetSymbolAddress((void**)&segb, g_seg);
    cudaGetSymbolAddress((void**)&cdb,  g_cd);
    cudaGetSymbolAddress((void**)&wt,   g_wt);
    cudaGetSymbolAddress((void**)&ahi,  g_ahi);
    cudaGetSymbolAddress((void**)&alo,  g_alo);
    cudaGetSymbolAddress((void**)&wih,  g_wih);
    cudaGetSymbolAddress((void**)&wil,  g_wil);
    cudaGetSymbolAddress((void**)&woh,  g_woh);
    cudaGetSymbolAddress((void**)&wol,  g_wol);

    const int SSD_SMEM = (3 * 64 * SMP + 3 * 64) * (int)sizeof(float);
    cudaFuncSetAttribute(ssd_chunk, cudaFuncAttributeMaxDynamicSharedMemorySize, SSD_SMEM);
    const int MG_SMEM = 2 * MG_STAGE;   // 61440
    cudaFuncSetAttribute(mma_gemm, cudaFuncAttributeMaxDynamicSharedMemorySize, MG_SMEM);

    // ---- front ----
    gemm128_nt<<<dim3(1, NTOK/128), 256>>>(x, pc_w, hmid, 128, 64, pc_b, 1);
    transpose_w<<<(256*128*3  + 255)/256, 256>>>(c1_w, wt,               3);
    transpose_w<<<(256*128*9  + 255)/256, 256>>>(c2_w, wt + 3*128*256,   9);
    transpose_w<<<(256*128*27 + 255)/256, 256>>>(c3_w, wt + 12*128*256, 27);
    conv_front<3> <<<dim3(4, NTOK/64), 256>>>(hmid, wt,               c1_b, h, ahi, alo, 0);
    conv_front<9> <<<dim3(4, NTOK/64), 256>>>(hmid, wt + 3*128*256,   c2_b, h, ahi, alo, 256);
    conv_front<27><<<dim3(4, NTOK/64), 256>>>(hmid, wt + 12*128*256,  c3_b, h, ahi, alo, 512);

    // ---- weight bf16 splits ----
    {
        int n4 = 4 * DINPROJ * DMODEL / 4;
        split_bf16<<<(n4 + 255)/256, 256>>>((const float4*)in_proj, wih, wil, n4);
        int m4 = 4 * DMODEL * DINNER / 4;
        split_bf16<<<(m4 + 255)/256, 256>>>((const float4*)out_proj, woh, wol, m4);
    }

    // ---- layers ----
    for (int l = 0; l < 4; l++) {
        mma_gemm<<<dim3((DINPROJ + 127)/128, NTOK/64), 128, MG_SMEM>>>(
            ahi, alo,
            wih + (size_t)l * DINPROJ * DMODEL, wil + (size_t)l * DINPROJ * DMODEL,
            zx, DINPROJ, DMODEL);
        dt_softplus<<<(NTOK*NHEADS + 255)/256, 256>>>(zx, dt_bias + l*NHEADS, dtb);
        dwconv<<<dim3((CONVDIM + 255)/256, NTOK), 256>>>(
            zx, conv_w + (size_t)l * CONVDIM * 4, conv_b + (size_t)l * CONVDIM, xBC);
        ssd_chunk<<<NBLK_SSD, 256, SSD_SMEM>>>(
            xBC, dtb, A_log + l*NHEADS, Dvec + l*NHEADS, ys, S, segb, cdb);
        ssd_scan<<<8*NHEADS, 256>>>(S, cdb);
        ssd_inter<<<NBLK_SSD, 256>>>(xBC, S, segb, ys);
        gate_rms<<<NTOK, 256>>>(ys, zx, norm_w + (size_t)l * DINNER, ahi, alo);
        mma_gemm<<<dim3(DMODEL/128, NTOK/64), 128, MG_SMEM>>>(
            ahi, alo,
            woh + (size_t)l * DMODEL * DINNER, wol + (size_t)l * DMODEL * DINNER,
            y2, DMODEL, DINNER);
        resid_ln<<<NTOK, 256>>>(y2, h, ln_w + (size_t)l * DMODEL, ln_b + (size_t)l * DMODEL,
                                ahi, alo);
    }

    // ---- head ----
    head_kernel<<<NTOK, 256>>>(h, fn_w, fn_b, lo_w, lo_b, out);
    (void)in_sizes; (void)n_in; (void)out_size;
}

// round 6
// speedup vs baseline: 2.3558x; 1.3370x over previous
#include <cuda_runtime.h>
#include <cuda_bf16.h>
#include <cstdint>
#include <math.h>

#define NTOK   16384
#define TLEN   2048
#define DMODEL 768
#define DINNER 1536
#define DSTATE 64
#define NHEADS 24
#define CONVDIM 1664
#define DINPROJ 3224
#define NCHUNK 32
#define NBLK_SSD (8*NCHUNK*NHEADS)   /* 6144 */
#define SMP 65

// ------------------------- scratch (device globals) -------------------------
__device__ float g_hmid[(size_t)NTOK*128];
__device__ float g_h   [(size_t)NTOK*DMODEL];
__device__ float g_zx  [(size_t)NTOK*DINPROJ];
__device__ float g_xBC [(size_t)NTOK*CONVDIM];
__device__ float g_dt  [(size_t)NTOK*NHEADS];
__device__ float g_ys  [(size_t)NTOK*DINNER];
__device__ float g_y2  [(size_t)NTOK*DMODEL];
__device__ float g_S   [(size_t)NBLK_SSD*4096];
__device__ float g_seg [(size_t)NBLK_SSD*64];
__device__ float g_cd  [NBLK_SSD];
__device__ float g_wt  [(size_t)(3+9+27)*128*256];   /* conv weights NT fp32 */
// bf16 split buffers
__device__ __nv_bfloat16 g_ahi[(size_t)NTOK*DINNER];
__device__ __nv_bfloat16 g_alo[(size_t)NTOK*DINNER];
__device__ __nv_bfloat16 g_hmh[(size_t)NTOK*128];
__device__ __nv_bfloat16 g_hml[(size_t)NTOK*128];
__device__ __nv_bfloat16 g_wch[(size_t)(3+9+27)*128*256];
__device__ __nv_bfloat16 g_wcl[(size_t)(3+9+27)*128*256];
__device__ __nv_bfloat16 g_wih[(size_t)4*DINPROJ*DMODEL];
__device__ __nv_bfloat16 g_wil[(size_t)4*DINPROJ*DMODEL];
__device__ __nv_bfloat16 g_woh[(size_t)4*DMODEL*DINNER];
__device__ __nv_bfloat16 g_wol[(size_t)4*DMODEL*DINNER];

// ------------------------- PTX helpers -------------------------
__device__ __forceinline__ uint32_t smem_u32(const void* p) {
    uint32_t a;
    asm("{ .reg .u64 t; cvta.to.shared.u64 t, %1; cvt.u32.u64 %0, t; }" : "=r"(a) : "l"(p));
    return a;
}
__device__ __forceinline__ void cp16z(uint32_t dst, const void* src, int srcsz) {
    asm volatile("cp.async.cg.shared.global [%0], [%1], 16, %2;" :: "r"(dst), "l"(src), "r"(srcsz));
}
__device__ __forceinline__ void ldsm4(uint32_t* r, uint32_t addr) {
    asm volatile("ldmatrix.sync.aligned.m8n8.x4.shared.b16 {%0,%1,%2,%3}, [%4];"
        : "=r"(r[0]), "=r"(r[1]), "=r"(r[2]), "=r"(r[3]) : "r"(addr));
}
__device__ __forceinline__ void mma16816(float* c, const uint32_t* a, const uint32_t* b) {
    asm volatile("mma.sync.aligned.m16n8k16.row.col.f32.bf16.bf16.f32 "
        "{%0,%1,%2,%3}, {%4,%5,%6,%7}, {%8,%9}, {%0,%1,%2,%3};"
        : "+f"(c[0]), "+f"(c[1]), "+f"(c[2]), "+f"(c[3])
        : "r"(a[0]), "r"(a[1]), "r"(a[2]), "r"(a[3]), "r"(b[0]), "r"(b[1]));
}
__device__ __forceinline__ void split1(float v, __nv_bfloat16& hi, __nv_bfloat16& lo) {
    hi = __float2bfloat16(v);
    lo = __float2bfloat16(v - __bfloat162float(hi));
}

// ------------------------- split fp32 -> bf16 hi/lo -------------------------
__global__ void split_bf16(const float4* __restrict__ src,
                           __nv_bfloat16* __restrict__ hi,
                           __nv_bfloat16* __restrict__ lo, int n4)
{
    int i = blockIdx.x * 256 + threadIdx.x;
    if (i >= n4) return;
    float4 v = src[i];
    float vv[4] = {v.x, v.y, v.z, v.w};
    __nv_bfloat16 h4[4], l4[4];
    #pragma unroll
    for (int j = 0; j < 4; j++) split1(vv[j], h4[j], l4[j]);
    uint2 hp, lp;
    hp.x = (uint32_t)*(uint16_t*)&h4[0] | ((uint32_t)*(uint16_t*)&h4[1] << 16);
    hp.y = (uint32_t)*(uint16_t*)&h4[2] | ((uint32_t)*(uint16_t*)&h4[3] << 16);
    lp.x = (uint32_t)*(uint16_t*)&l4[0] | ((uint32_t)*(uint16_t*)&l4[1] << 16);
    lp.y = (uint32_t)*(uint16_t*)&l4[2] | ((uint32_t)*(uint16_t*)&l4[3] << 16);
    *reinterpret_cast<uint2*>(hi + (size_t)i * 4) = hp;
    *reinterpret_cast<uint2*>(lo + (size_t)i * 4) = lp;
}

// ------------------------- mma.sync split-bf16 NT GEMM, 64x128 tile -------------------------
#define MG_PITCH 80
#define MG_AMAT  5120
#define MG_BBASE 10240
#define MG_BMAT  10240
#define MG_STAGE 30720

__device__ __forceinline__ void mg_load(
    uint32_t sbase,
    const __nv_bfloat16* __restrict__ Ah, const __nv_bfloat16* __restrict__ Al,
    const __nv_bfloat16* __restrict__ Bh, const __nv_bfloat16* __restrict__ Bl,
    int m0, int n0, int Ntot, int K, int c, int tid)
{
    #pragma unroll
    for (int j = 0; j < 4; j++) {
        int e = tid + j * 128;
        int seg = e & 3, r = (e >> 2) & 63, mat = e >> 8;
        uint32_t soff = (uint32_t)(mat * MG_AMAT + r * MG_PITCH + seg * 16);
        const __nv_bfloat16* src = (mat ? Al : Ah) + (size_t)(m0 + r) * K + (size_t)c * 32 + seg * 8;
        cp16z(sbase + soff, src, 16);
    }
    #pragma unroll
    for (int j = 0; j < 8; j++) {
        int e = tid + j * 128;
        int seg = e & 3, r = (e >> 2) & 127, mat = e >> 9;
        uint32_t soff = (uint32_t)(MG_BBASE + mat * MG_BMAT + r * MG_PITCH + seg * 16);
        int nr = n0 + r;
        int sz = (nr < Ntot) ? 16 : 0;
        int nrc = (nr < Ntot) ? nr : 0;
        const __nv_bfloat16* src = (mat ? Bl : Bh) + (size_t)nrc * K + (size_t)c * 32 + seg * 8;
        cp16z(sbase + soff, src, sz);
    }
    asm volatile("cp.async.commit_group;" ::: "memory");
}

__global__ __launch_bounds__(128, 3) void mma_gemm(
    const __nv_bfloat16* __restrict__ Ah, const __nv_bfloat16* __restrict__ Al,
    const __nv_bfloat16* __restrict__ Bh, const __nv_bfloat16* __restrict__ Bl,
    float* __restrict__ C, int Ntot, int K)
{
    extern __shared__ char smem[];
    uint32_t sb = smem_u32(smem);
    int tid = threadIdx.x, wid = tid >> 5, lane = tid & 31;
    int m0 = blockIdx.y * 64, n0 = blockIdx.x * 128;
    int wm = (wid >> 1) * 32;
    int wn = (wid & 1) * 64;

    float acc[2][8][4];
    #pragma unroll
    for (int a = 0; a < 2; a++)
        #pragma unroll
        for (int b = 0; b < 8; b++)
            #pragma unroll
            for (int q = 0; q < 4; q++) acc[a][b][q] = 0.f;

    int gr = lane >> 3, lr = lane & 7;
    int arow = (gr & 1) * 8 + lr;
    int acol = (gr >> 1) * 16;
    int brow = (gr >> 1) * 8 + lr;
    int bcol = (gr & 1) * 16;

    int nch = K >> 5;
    mg_load(sb, Ah, Al, Bh, Bl, m0, n0, Ntot, K, 0, tid);
    for (int c = 0; c < nch; c++) {
        if (c + 1 < nch) {
            mg_load(sb + ((c + 1) & 1) * MG_STAGE, Ah, Al, Bh, Bl, m0, n0, Ntot, K, c + 1, tid);
            asm volatile("cp.async.wait_group 1;" ::: "memory");
        } else {
            asm volatile("cp.async.wait_group 0;" ::: "memory");
        }
        __syncthreads();
        uint32_t base = sb + (uint32_t)(c & 1) * MG_STAGE;
        #pragma unroll
        for (int ks = 0; ks < 2; ks++) {
            uint32_t ah[2][4], al[2][4];
            #pragma unroll
            for (int mt = 0; mt < 2; mt++) {
                uint32_t off = (uint32_t)((wm + mt*16 + arow) * MG_PITCH + acol + ks*32);
                ldsm4(ah[mt], base + off);
                ldsm4(al[mt], base + MG_AMAT + off);
            }
            uint32_t bh[4][4], bl[4][4];
            #pragma unroll
            for (int np = 0; np < 4; np++) {
                uint32_t off = (uint32_t)(MG_BBASE + (wn + np*16 + brow) * MG_PITCH + bcol + ks*32);
                ldsm4(bh[np], base + off);
                ldsm4(bl[np], base + MG_BMAT + off);
            }
            #pragma unroll
            for (int mt = 0; mt < 2; mt++)
                #pragma unroll
                for (int np = 0; np < 4; np++) {
                    mma16816(acc[mt][2*np],   ah[mt], &bh[np][0]);
                    mma16816(acc[mt][2*np+1], ah[mt], &bh[np][2]);
                    mma16816(acc[mt][2*np],   ah[mt], &bl[np][0]);
                    mma16816(acc[mt][2*np+1], ah[mt], &bl[np][2]);
                    mma16816(acc[mt][2*np],   al[mt], &bh[np][0]);
                    mma16816(acc[mt][2*np+1], al[mt], &bh[np][2]);
                }
        }
        __syncthreads();
    }

    int r4 = lane >> 2, c2 = (lane & 3) * 2;
    #pragma unroll
    for (int mt = 0; mt < 2; mt++) {
        int r = m0 + wm + mt*16 + r4;
        #pragma unroll
        for (int nt = 0; nt < 8; nt++) {
            int col = n0 + wn + nt*8 + c2;
            if (col < Ntot) {
                float* cc = acc[mt][nt];
                *(float2*)&C[(size_t)r * Ntot + col]       = make_float2(cc[0], cc[1]);
                *(float2*)&C[(size_t)(r + 8) * Ntot + col] = make_float2(cc[2], cc[3]);
            }
        }
    }
}

// ------------------------- mma conv (implicit im2col), 64x128 tile, N=256 -------------------------
// A = hmid splits [NTOK][128] with per-tap row shift; B = wconv splits [256][KTAP*128].
template<int KTAP>
__device__ __forceinline__ void mg_load_conv(
    uint32_t sbase,
    const __nv_bfloat16* __restrict__ Ah, const __nv_bfloat16* __restrict__ Al,
    const __nv_bfloat16* __restrict__ Bh, const __nv_bfloat16* __restrict__ Bl,
    int m0, int n0, int c, int tid)
{
    const int PAD = KTAP / 2;
    const int K = KTAP * 128;
    int tap = c >> 2;
    int ch0 = (c & 3) * 32;
    #pragma unroll
    for (int j = 0; j < 4; j++) {
        int e = tid + j * 128;
        int seg = e & 3, r = (e >> 2) & 63, mat = e >> 8;
        uint32_t soff = (uint32_t)(mat * MG_AMAT + r * MG_PITCH + seg * 16);
        int tg = m0 + r;
        int tsrc = (tg & (TLEN - 1)) + tap - PAD;
        int valid = (tsrc >= 0 && tsrc < TLEN);
        size_t gidx = valid ? ((size_t)(tg + tap - PAD) * 128 + ch0 + seg * 8) : 0;
        const __nv_bfloat16* src = (mat ? Al : Ah) + gidx;
        cp16z(sbase + soff, src, valid ? 16 : 0);
    }
    #pragma unroll
    for (int j = 0; j < 8; j++) {
        int e = tid + j * 128;
        int seg = e & 3, r = (e >> 2) & 127, mat = e >> 9;
        uint32_t soff = (uint32_t)(MG_BBASE + mat * MG_BMAT + r * MG_PITCH + seg * 16);
        const __nv_bfloat16* src = (mat ? Bl : Bh) + (size_t)(n0 + r) * K + (size_t)c * 32 + seg * 8;
        cp16z(sbase + soff, src, 16);
    }
    asm volatile("cp.async.commit_group;" ::: "memory");
}

template<int KTAP>
__global__ __launch_bounds__(128, 3) void mma_conv(
    const __nv_bfloat16* __restrict__ Ah, const __nv_bfloat16* __restrict__ Al,
    const __nv_bfloat16* __restrict__ Bh, const __nv_bfloat16* __restrict__ Bl,
    const float* __restrict__ bias, float* __restrict__ Hout,
    __nv_bfloat16* __restrict__ ohi, __nv_bfloat16* __restrict__ olo, int colofs)
{
    extern __shared__ char smem[];
    uint32_t sb = smem_u32(smem);
    int tid = threadIdx.x, wid = tid >> 5, lane = tid & 31;
    int m0 = blockIdx.y * 64, n0 = blockIdx.x * 128;
    int wm = (wid >> 1) * 32;
    int wn = (wid & 1) * 64;

    float acc[2][8][4];
    #pragma unroll
    for (int a = 0; a < 2; a++)
        #pragma unroll
        for (int b = 0; b < 8; b++)
            #pragma unroll
            for (int q = 0; q < 4; q++) acc[a][b][q] = 0.f;

    int gr = lane >> 3, lr = lane & 7;
    int arow = (gr & 1) * 8 + lr;
    int acol = (gr >> 1) * 16;
    int brow = (gr >> 1) * 8 + lr;
    int bcol = (gr & 1) * 16;

    const int nch = KTAP * 4;
    mg_load_conv<KTAP>(sb, Ah, Al, Bh, Bl, m0, n0, 0, tid);
    for (int c = 0; c < nch; c++) {
        if (c + 1 < nch) {
            mg_load_conv<KTAP>(sb + ((c + 1) & 1) * MG_STAGE, Ah, Al, Bh, Bl, m0, n0, c + 1, tid);
            asm volatile("cp.async.wait_group 1;" ::: "memory");
        } else {
            asm volatile("cp.async.wait_group 0;" ::: "memory");
        }
        __syncthreads();
        uint32_t base = sb + (uint32_t)(c & 1) * MG_STAGE;
        #pragma unroll
        for (int ks = 0; ks < 2; ks++) {
            uint32_t ah[2][4], al[2][4];
            #pragma unroll
            for (int mt = 0; mt < 2; mt++) {
                uint32_t off = (uint32_t)((wm + mt*16 + arow) * MG_PITCH + acol + ks*32);
                ldsm4(ah[mt], base + off);
                ldsm4(al[mt], base + MG_AMAT + off);
            }
            uint32_t bh[4][4], bl[4][4];
            #pragma unroll
            for (int np = 0; np < 4; np++) {
                uint32_t off = (uint32_t)(MG_BBASE + (wn + np*16 + brow) * MG_PITCH + bcol + ks*32);
                ldsm4(bh[np], base + off);
                ldsm4(bl[np], base + MG_BMAT + off);
            }
            #pragma unroll
            for (int mt = 0; mt < 2; mt++)
                #pragma unroll
                for (int np = 0; np < 4; np++) {
                    mma16816(acc[mt][2*np],   ah[mt], &bh[np][0]);
                    mma16816(acc[mt][2*np+1], ah[mt], &bh[np][2]);
                    mma16816(acc[mt][2*np],   ah[mt], &bl[np][0]);
                    mma16816(acc[mt][2*np+1], ah[mt], &bl[np][2]);
                    mma16816(acc[mt][2*np],   al[mt], &bh[np][0]);
                    mma16816(acc[mt][2*np+1], al[mt], &bh[np][2]);
                }
        }
        __syncthreads();
    }

    int r4 = lane >> 2, c2 = (lane & 3) * 2;
    #pragma unroll
    for (int mt = 0; mt < 2; mt++) {
        #pragma unroll
        for (int half = 0; half < 2; half++) {
            int r = m0 + wm + mt*16 + r4 + half*8;
            #pragma unroll
            for (int nt = 0; nt < 8; nt++) {
                int col = n0 + wn + nt*8 + c2;
                float* cc = acc[mt][nt];
                #pragma unroll
                for (int q = 0; q < 2; q++) {
                    float v = cc[half*2 + q] + bias[col + q];
                    v = v / (1.f + expf(-v));
                    size_t idx = (size_t)r * DMODEL + colofs + col + q;
                    Hout[idx] = v;
                    __nv_bfloat16 hi, lo;
                    split1(v, hi, lo);
                    ohi[idx] = hi;
                    olo[idx] = lo;
                }
            }
        }
    }
}

// ------------------------- helpers -------------------------
__device__ __forceinline__ float blockReduceSum(float v, float* red) {
    int tid = threadIdx.x;
    #pragma unroll
    for (int o = 16; o; o >>= 1) v += __shfl_xor_sync(0xffffffffu, v, o);
    if ((tid & 31) == 0) red[tid >> 5] = v;
    __syncthreads();
    if (tid < 32) {
        float w = (tid < 8) ? red[tid] : 0.f;
        #pragma unroll
        for (int o = 4; o; o >>= 1) w += __shfl_xor_sync(0xffffffffu, w, o);
        if (tid == 0) red[0] = w;
    }
    __syncthreads();
    float r0 = red[0];
    __syncthreads();
    return r0;
}

// ------------------------- front 1x1 conv SGEMM (writes hmid + bf16 split) -------------------------
__global__ __launch_bounds__(256) void gemm128_nt(
    const float* __restrict__ A, const float* __restrict__ B,
    float* __restrict__ C, int N, int K,
    const float* __restrict__ bias,
    __nv_bfloat16* __restrict__ ohi, __nv_bfloat16* __restrict__ olo)
{
    __shared__ float As[8][128];
    __shared__ float Bs[8][128];
    int m0 = blockIdx.y * 128, n0 = blockIdx.x * 128;
    int tid = threadIdx.x;
    int tx = tid & 15, ty = tid >> 4;
    float acc[8][8] = {};
    int lr = tid >> 1;
    int lk = (tid & 1) * 4;
    const float* Ag = A + (size_t)(m0 + lr) * K + lk;
    const float* Bg = B + (size_t)(n0 + lr) * K + lk;
    bool bvalid = (n0 + lr) < N;
    for (int k0 = 0; k0 < K; k0 += 8) {
        float4 av = *(const float4*)(Ag + k0);
        float4 bv = bvalid ? *(const float4*)(Bg + k0) : make_float4(0.f,0.f,0.f,0.f);
        __syncthreads();
        As[lk+0][lr] = av.x; As[lk+1][lr] = av.y; As[lk+2][lr] = av.z; As[lk+3][lr] = av.w;
        Bs[lk+0][lr] = bv.x; Bs[lk+1][lr] = bv.y; Bs[lk+2][lr] = bv.z; Bs[lk+3][lr] = bv.w;
        __syncthreads();
        #pragma unroll
        for (int kk = 0; kk < 8; kk++) {
            float4 a0 = *(const float4*)&As[kk][ty*8];
            float4 a1 = *(const float4*)&As[kk][ty*8+4];
            float4 b0 = *(const float4*)&Bs[kk][tx*8];
            float4 b1 = *(const float4*)&Bs[kk][tx*8+4];
            float a[8] = {a0.x,a0.y,a0.z,a0.w,a1.x,a1.y,a1.z,a1.w};
            float b[8] = {b0.x,b0.y,b0.z,b0.w,b1.x,b1.y,b1.z,b1.w};
            #pragma unroll
            for (int r = 0; r < 8; r++)
                #pragma unroll
                for (int s = 0; s < 8; s++) acc[r][s] += a[r]*b[s];
        }
    }
    #pragma unroll
    for (int r = 0; r < 8; r++) {
        int m = m0 + ty*8 + r;
        #pragma unroll
        for (int s = 0; s < 8; s++) {
            int n = n0 + tx*8 + s;
            if (n < N) {
                float v = acc[r][s] + bias[n];
                v = v / (1.f + expf(-v));
                size_t idx = (size_t)m * N + n;
                C[idx] = v;
                __nv_bfloat16 hi, lo;
                split1(v, hi, lo);
                ohi[idx] = hi;
                olo[idx] = lo;
            }
        }
    }
}

// ------------------------- conv weight NT transpose: wt[o][tap*128+i] = w[o][i][tap] -------------------------
__global__ void transpose_wc(const float* __restrict__ w, float* __restrict__ wt, int KTAP)
{
    int idx = blockIdx.x * 256 + threadIdx.x;
    int K = KTAP * 128;
    int total = 256 * K;
    if (idx >= total) return;
    int o = idx / K;
    int kk = idx - o * K;
    int tap = kk >> 7;
    int i = kk & 127;
    wt[idx] = w[(size_t)o * 128 * KTAP + (size_t)i * KTAP + tap];
}

// ------------------------- dt softplus -------------------------
__global__ void dt_softplus(const float* __restrict__ zx, const float* __restrict__ dtb,
                            float* __restrict__ dt)
{
    int idx = blockIdx.x * 256 + threadIdx.x;
    if (idx >= NTOK * NHEADS) return;
    int t = idx / NHEADS, hh = idx - t * NHEADS;
    float x = zx[(size_t)t * DINPROJ + 3200 + hh] + dtb[hh];
    dt[idx] = (x > 20.f) ? x : log1pf(expf(x));
}

// ------------------------- depthwise causal conv + silu (4 tokens/thread) -------------------------
__global__ void dwconv4(const float* __restrict__ zx, const float* __restrict__ cw,
                        const float* __restrict__ cb, float* __restrict__ xBC)
{
    int c = blockIdx.x * 256 + threadIdx.x;
    if (c >= CONVDIM) return;
    int t0 = blockIdx.y * 4;
    int ti0 = t0 & (TLEN - 1);
    float4 w = *(const float4*)(cw + (size_t)c * 4);
    float bias = cb[c];
    float z[7];
    #pragma unroll
    for (int j = 0; j < 7; j++) {
        int ti = ti0 - 3 + j;
        z[j] = (ti >= 0) ? zx[(size_t)(t0 - 3 + j) * DINPROJ + DINNER + c] : 0.f;
    }
    #pragma unroll
    for (int j = 0; j < 4; j++) {
        float acc = bias + z[j]*w.x + z[j+1]*w.y + z[j+2]*w.z + z[j+3]*w.w;
        xBC[(size_t)(t0 + j) * CONVDIM + c] = acc / (1.f + expf(-acc));
    }
}

// ------------------------- SSD per-chunk kernel -------------------------
__global__ __launch_bounds__(256) void ssd_chunk(
    const float* __restrict__ xBC, const float* __restrict__ dt,
    const float* __restrict__ A_log, const float* __restrict__ Dv,
    float* __restrict__ ys, float* __restrict__ Sg,
    float* __restrict__ segout, float* __restrict__ cdout)
{
    extern __shared__ float sm[];
    float* Bs  = sm;
    float* Cs  = Bs + 64*SMP;
    float* Ds  = Cs + 64*SMP;
    float* seg = Ds + 64*SMP;
    float* dec = seg + 64;
    float* dts = dec + 64;

    int blk = blockIdx.x;
    int h = blk % NHEADS;
    int c = (blk / NHEADS) & (NCHUNK - 1);
    int b = blk / (NHEADS * NCHUNK);
    int t0 = b * TLEN + c * 64;
    int tid = threadIdx.x;
    float A = -expf(A_log[h]);

    if (tid < 64) dts[tid] = dt[(size_t)(t0 + tid) * NHEADS + h];
    __syncthreads();
    for (int e = tid; e < 4096; e += 256) {
        int j = e >> 6, n = e & 63;
        const float* row = xBC + (size_t)(t0 + j) * CONVDIM;
        Bs[j*SMP + n] = row[DINNER + n];
        Cs[j*SMP + n] = row[DINNER + DSTATE + n];
        Ds[j*SMP + n] = dts[j] * row[h*64 + n];
    }
    if (tid < 64) seg[tid] = dts[tid] * A;
    __syncthreads();
    for (int off = 1; off < 64; off <<= 1) {
        float v = 0.f;
        bool act = (tid < 64) && (tid >= off);
        if (act) v = seg[tid - off];
        __syncthreads();
        if (act) seg[tid] += v;
        __syncthreads();
    }
    if (tid < 64) {
        dec[tid] = expf(seg[63] - seg[tid]);
        segout[(size_t)blk * 64 + tid] = seg[tid];
    }
    if (tid == 0) cdout[blk] = expf(seg[63]);
    __syncthreads();

    int tx = tid & 15, ty = tid >> 4;
    float acc[4][4] = {};
    #pragma unroll 4
    for (int n = 0; n < 64; n++) {
        float a[4], bb[4];
        #pragma unroll
        for (int r = 0; r < 4; r++) a[r] = Cs[(ty*4 + r)*SMP + n];
        #pragma unroll
        for (int s = 0; s < 4; s++) bb[s] = Bs[(tx*4 + s)*SMP + n];
        #pragma unroll
        for (int r = 0; r < 4; r++)
            #pragma unroll
            for (int s = 0; s < 4; s++) acc[r][s] += a[r]*bb[s];
    }
    __syncthreads();
    #pragma unroll
    for (int r = 0; r < 4; r++)
        #pragma unroll
        for (int s = 0; s < 4; s++) {
            int i = ty*4 + r, j = tx*4 + s;
            float v = 0.f;
            if (i >= j) v = expf(seg[i] - seg[j]) * acc[r][s];
            Cs[i*SMP + j] = v;
        }
    __syncthreads();
    float acc2[4][4] = {};
    #pragma unroll 4
    for (int j = 0; j < 64; j++) {
        float a[4], bb[4];
        #pragma unroll
        for (int r = 0; r < 4; r++) a[r] = Cs[(ty*4 + r)*SMP + j];
        #pragma unroll
        for (int s = 0; s < 4; s++) bb[s] = Ds[j*SMP + tx*4 + s];
        #pragma unroll
        for (int r = 0; r < 4; r++)
            #pragma unroll
            for (int s = 0; s < 4; s++) acc2[r][s] += a[r]*bb[s];
    }
    float Dh = Dv[h];
    #pragma unroll
    for (int r = 0; r < 4; r++)
        #pragma unroll
        for (int s = 0; s < 4; s++) {
            int i = t0 + ty*4 + r;
            int p = tx*4 + s;
            ys[(size_t)i * DINNER + h*64 + p] =
                acc2[r][s] + Dh * xBC[(size_t)i * CONVDIM + h*64 + p];
        }
    float acc3[4][4] = {};
    #pragma unroll 4
    for (int j = 0; j < 64; j++) {
        float dj = dec[j];
        float a[4], bb[4];
        #pragma unroll
        for (int r = 0; r < 4; r++) a[r] = Ds[j*SMP + ty*4 + r] * dj;
        #pragma unroll
        for (int s = 0; s < 4; s++) bb[s] = Bs[j*SMP + tx*4 + s];
        #pragma unroll
        for (int r = 0; r < 4; r++)
            #pragma unroll
            for (int s = 0; s < 4; s++) acc3[r][s] += a[r]*bb[s];
    }
    #pragma unroll
    for (int r = 0; r < 4; r++)
        #pragma unroll
        for (int s = 0; s < 4; s++)
            Sg[(size_t)blk * 4096 + (ty*4 + r)*64 + tx*4 + s] = acc3[r][s];
}

// ------------------------- inter-chunk scan (8-way partitioned) -------------------------
__global__ __launch_bounds__(256) void ssd_scan8(float* __restrict__ Sg,
                                                 const float* __restrict__ cd)
{
    int blk = blockIdx.x;            // 1536 = 8*24*8parts
    int part = blk & 7;
    int bh = blk >> 3;
    int h = bh % NHEADS, b = bh / NHEADS;
    int tid = threadIdx.x;
    int e0 = part * 512 + tid;
    float st0 = 0.f, st1 = 0.f;
    for (int c = 0; c < NCHUNK; c++) {
        int bidx = (b * NCHUNK + c) * NHEADS + h;
        size_t base = (size_t)bidx * 4096;
        float d = cd[bidx];
        float s0 = Sg[base + e0];
        float s1 = Sg[base + e0 + 256];
        Sg[base + e0]       = st0;
        Sg[base + e0 + 256] = st1;
        st0 = st0 * d + s0;
        st1 = st1 * d + s1;
    }
}

// ------------------------- y_inter accumulation -------------------------
__global__ __launch_bounds__(256) void ssd_inter(
    const float* __restrict__ xBC, const float* __restrict__ Sg,
    const float* __restrict__ segin, float* __restrict__ ys)
{
    __shared__ float Cs[64*SMP];
    __shared__ float Hs[64*SMP];
    __shared__ float seg[64];
    int blk = blockIdx.x;
    int h = blk % NHEADS;
    int c = (blk / NHEADS) & (NCHUNK - 1);
    int b = blk / (NHEADS * NCHUNK);
    int t0 = b * TLEN + c * 64;
    int tid = threadIdx.x;
    for (int e = tid; e < 4096; e += 256) {
        int j = e >> 6, n = e & 63;
        Cs[j*SMP + n] = xBC[(size_t)(t0 + j) * CONVDIM + DINNER + DSTATE + n];
        Hs[j*SMP + n] = Sg[(size_t)blk * 4096 + j*64 + n];
    }
    if (tid < 64) seg[tid] = segin[(size_t)blk * 64 + tid];
    __syncthreads();
    int tx = tid & 15, ty = tid >> 4;
    float acc[4][4] = {};
    #pragma unroll 4
    for (int n = 0; n < 64; n++) {
        float a[4], bb[4];
        #pragma unroll
        for (int r = 0; r < 4; r++) a[r] = Cs[(ty*4 + r)*SMP + n];
        #pragma unroll
        for (int s = 0; s < 4; s++) bb[s] = Hs[(tx*4 + s)*SMP + n];
        #pragma unroll
        for (int r = 0; r < 4; r++)
            #pragma unroll
            for (int s = 0; s < 4; s++) acc[r][s] += a[r]*bb[s];
    }
    #pragma unroll
    for (int r = 0; r < 4; r++) {
        float ei = expf(seg[ty*4 + r]);
        #pragma unroll
        for (int s = 0; s < 4; s++) {
            size_t idx = (size_t)(t0 + ty*4 + r) * DINNER + h*64 + tx*4 + s;
            ys[idx] += acc[r][s] * ei;
        }
    }
}

// ------------------------- gating + RMSNorm (writes bf16 split) -------------------------
__global__ __launch_bounds__(256) void gate_rms(
    const float* __restrict__ ys, const float* __restrict__ zx,
    const float* __restrict__ nw,
    __nv_bfloat16* __restrict__ ohi, __nv_bfloat16* __restrict__ olo)
{
    __shared__ float red[32];
    int t = blockIdx.x, tid = threadIdx.x;
    float v[6];
    float ss = 0.f;
    #pragma unroll
    for (int r = 0; r < 6; r++) {
        int i = tid + r*256;
        float z = zx[(size_t)t * DINPROJ + i];
        float val = ys[(size_t)t * DINNER + i] * (z / (1.f + expf(-z)));
        v[r] = val;
        ss += val*val;
    }
    ss = blockReduceSum(ss, red);
    float sc = rsqrtf(ss / (float)DINNER + 1e-5f);
    #pragma unroll
    for (int r = 0; r < 6; r++) {
        int i = tid + r*256;
        float val = v[r] * sc * nw[i];
        __nv_bfloat16 hi, lo;
        split1(val, hi, lo);
        size_t idx = (size_t)t * DINNER + i;
        ohi[idx] = hi;
        olo[idx] = lo;
    }
}

// ------------------------- residual + layernorm (writes h + bf16 split) -------------------------
__global__ __launch_bounds__(256) void resid_ln(
    const float* __restrict__ y2, float* __restrict__ hio,
    const float* __restrict__ w, const float* __restrict__ b,
    __nv_bfloat16* __restrict__ ohi, __nv_bfloat16* __restrict__ olo)
{
    __shared__ float red[32];
    int t = blockIdx.x, tid = threadIdx.x;
    float v[3];
    float s = 0.f;
    #pragma unroll
    for (int r = 0; r < 3; r++) {
        int i = tid + r*256;
        v[r] = y2[(size_t)t * DMODEL + i] + hio[(size_t)t * DMODEL + i];
        s += v[r];
    }
    s = blockReduceSum(s, red);
    float mean = s / (float)DMODEL;
    float q = 0.f;
    #pragma unroll
    for (int r = 0; r < 3; r++) { v[r] -= mean; q += v[r]*v[r]; }
    q = blockReduceSum(q, red);
    float inv = rsqrtf(q / (float)DMODEL + 1e-5f);
    #pragma unroll
    for (int r = 0; r < 3; r++) {
        int i = tid + r*256;
        float val = v[r] * inv * w[i] + b[i];
        size_t idx = (size_t)t * DMODEL + i;
        hio[idx] = val;
        __nv_bfloat16 hi, lo;
        split1(val, hi, lo);
        ohi[idx] = hi;
        olo[idx] = lo;
    }
}

// ------------------------- final layernorm + logits -------------------------
__global__ __launch_bounds__(256) void head_kernel(
    const float* __restrict__ hin,
    const float* __restrict__ fw, const float* __restrict__ fb,
    const float* __restrict__ lw, const float* __restrict__ lb,
    float* __restrict__ out)
{
    __shared__ float red[32];
    __shared__ float buf[DMODEL];
    int t = blockIdx.x, tid = threadIdx.x;
    float v[3];
    float s = 0.f;
    #pragma unroll
    for (int r = 0; r < 3; r++) {
        int i = tid + r*256;
        v[r] = hin[(size_t)t * DMODEL + i];
        s += v[r];
    }
    s = blockReduceSum(s, red);
    float mean = s / (float)DMODEL;
    float q = 0.f;
    #pragma unroll
    for (int r = 0; r < 3; r++) { v[r] -= mean; q += v[r]*v[r]; }
    q = blockReduceSum(q, red);
    float inv = rsqrtf(q / (float)DMODEL + 1e-5f);
    #pragma unroll
    for (int r = 0; r < 3; r++) {
        int i = tid + r*256;
        buf[i] = v[r] * inv * fw[i] + fb[i];
    }
    __syncthreads();
    for (int cls = 0; cls < 10; cls++) {
        float p = 0.f;
        #pragma unroll
        for (int r = 0; r < 3; r++) {
            int i = tid + r*256;
            p += buf[i] * lw[(size_t)cls * DMODEL + i];
        }
        p = blockReduceSum(p, red);
        if (tid == 0) out[(size_t)t * 10 + cls] = p + lb[cls];
    }
}

// ------------------------- launch -------------------------
extern "C" void kernel_launch(void* const* d_in, const int* in_sizes, int n_in,
                              void* d_out, int out_size)
{
    const float* x       = (const float*)d_in[0];
    const float* pc_w    = (const float*)d_in[1];
    const float* pc_b    = (const float*)d_in[2];
    const float* c1_w    = (const float*)d_in[3];
    const float* c1_b    = (const float*)d_in[4];
    const float* c2_w    = (const float*)d_in[5];
    const float* c2_b    = (const float*)d_in[6];
    const float* c3_w    = (const float*)d_in[7];
    const float* c3_b    = (const float*)d_in[8];
    const float* in_proj = (const float*)d_in[9];
    const float* conv_w  = (const float*)d_in[10];
    const float* conv_b  = (const float*)d_in[11];
    const float* dt_bias = (const float*)d_in[12];
    const float* A_log   = (const float*)d_in[13];
    const float* Dvec    = (const float*)d_in[14];
    const float* norm_w  = (const float*)d_in[15];
    const float* out_proj= (const float*)d_in[16];
    const float* ln_w    = (const float*)d_in[17];
    const float* ln_b    = (const float*)d_in[18];
    const float* fn_w    = (const float*)d_in[19];
    const float* fn_b    = (const float*)d_in[20];
    const float* lo_w    = (const float*)d_in[21];
    const float* lo_b    = (const float*)d_in[22];
    float* out = (float*)d_out;

    float *hmid, *h, *zx, *xBC, *dtb, *ys, *y2, *S, *segb, *cdb, *wt;
    __nv_bfloat16 *ahi, *alo, *hmh, *hml, *wch, *wcl, *wih, *wil, *woh, *wol;
    cudaGetSymbolAddress((void**)&hmid, g_hmid);
    cudaGetSymbolAddress((void**)&h,    g_h);
    cudaGetSymbolAddress((void**)&zx,   g_zx);
    cudaGetSymbolAddress((void**)&xBC,  g_xBC);
    cudaGetSymbolAddress((void**)&dtb,  g_dt);
    cudaGetSymbolAddress((void**)&ys,   g_ys);
    cudaGetSymbolAddress((void**)&y2,   g_y2);
    cudaGetSymbolAddress((void**)&S,    g_S);
    cudaGetSymbolAddress((void**)&segb, g_seg);
    cudaGetSymbolAddress((void**)&cdb,  g_cd);
    cudaGetSymbolAddress((void**)&wt,   g_wt);
    cudaGetSymbolAddress((void**)&ahi,  g_ahi);
    cudaGetSymbolAddress((void**)&alo,  g_alo);
    cudaGetSymbolAddress((void**)&hmh,  g_hmh);
    cudaGetSymbolAddress((void**)&hml,  g_hml);
    cudaGetSymbolAddress((void**)&wch,  g_wch);
    cudaGetSymbolAddress((void**)&wcl,  g_wcl);
    cudaGetSymbolAddress((void**)&wih,  g_wih);
    cudaGetSymbolAddress((void**)&wil,  g_wil);
    cudaGetSymbolAddress((void**)&woh,  g_woh);
    cudaGetSymbolAddress((void**)&wol,  g_wol);

    const int SSD_SMEM = (3 * 64 * SMP + 3 * 64) * (int)sizeof(float);
    cudaFuncSetAttribute(ssd_chunk, cudaFuncAttributeMaxDynamicSharedMemorySize, SSD_SMEM);
    const int MG_SMEM = 2 * MG_STAGE;   // 61440
    cudaFuncSetAttribute(mma_gemm, cudaFuncAttributeMaxDynamicSharedMemorySize, MG_SMEM);
    cudaFuncSetAttribute(mma_conv<3>,  cudaFuncAttributeMaxDynamicSharedMemorySize, MG_SMEM);
    cudaFuncSetAttribute(mma_conv<9>,  cudaFuncAttributeMaxDynamicSharedMemorySize, MG_SMEM);
    cudaFuncSetAttribute(mma_conv<27>, cudaFuncAttributeMaxDynamicSharedMemorySize, MG_SMEM);

    // ---- front ----
    gemm128_nt<<<dim3(1, NTOK/128), 256>>>(x, pc_w, hmid, 128, 64, pc_b, hmh, hml);
    transpose_wc<<<(256*384  + 255)/256, 256>>>(c1_w, wt,           3);
    transpose_wc<<<(256*1152 + 255)/256, 256>>>(c2_w, wt + 98304,   9);
    transpose_wc<<<(256*3456 + 255)/256, 256>>>(c3_w, wt + 393216, 27);
    split_bf16<<<(1277952/4 + 255)/256, 256>>>((const float4*)wt, wch, wcl, 1277952/4);
    mma_conv<3> <<<dim3(2, NTOK/64), 128, MG_SMEM>>>(hmh, hml, wch,          wcl,          c1_b, h, ahi, alo, 0);
    mma_conv<9> <<<dim3(2, NTOK/64), 128, MG_SMEM>>>(hmh, hml, wch + 98304,  wcl + 98304,  c2_b, h, ahi, alo, 256);
    mma_conv<27><<<dim3(2, NTOK/64), 128, MG_SMEM>>>(hmh, hml, wch + 393216, wcl + 393216, c3_b, h, ahi, alo, 512);

    // ---- weight bf16 splits ----
    {
        int n4 = 4 * DINPROJ * DMODEL / 4;
        split_bf16<<<(n4 + 255)/256, 256>>>((const float4*)in_proj, wih, wil, n4);
        int m4 = 4 * DMODEL * DINNER / 4;
        split_bf16<<<(m4 + 255)/256, 256>>>((const float4*)out_proj, woh, wol, m4);
    }

    // ---- layers ----
    for (int l = 0; l < 4; l++) {
        mma_gemm<<<dim3((DINPROJ + 127)/128, NTOK/64), 128, MG_SMEM>>>(
            ahi, alo,
            wih + (size_t)l * DINPROJ * DMODEL, wil + (size_t)l * DINPROJ * DMODEL,
            zx, DINPROJ, DMODEL);
        dt_softplus<<<(NTOK*NHEADS + 255)/256, 256>>>(zx, dt_bias + l*NHEADS, dtb);
        dwconv4<<<dim3((CONVDIM + 255)/256, NTOK/4), 256>>>(
            zx, conv_w + (size_t)l * CONVDIM * 4, conv_b + (size_t)l * CONVDIM, xBC);
        ssd_chunk<<<NBLK_SSD, 256, SSD_SMEM>>>(
            xBC, dtb, A_log + l*NHEADS, Dvec + l*NHEADS, ys, S, segb, cdb);
        ssd_scan8<<<8*NHEADS*8, 256>>>(S, cdb);
        ssd_inter<<<NBLK_SSD, 256>>>(xBC, S, segb, ys);
        gate_rms<<<NTOK, 256>>>(ys, zx, norm_w + (size_t)l * DINNER, ahi, alo);
        mma_gemm<<<dim3(DMODEL/128, NTOK/64), 128, MG_SMEM>>>(
            ahi, alo,
            woh + (size_t)l * DMODEL * DINNER, wol + (size_t)l * DMODEL * DINNER,
            y2, DMODEL, DINNER);
        resid_ln<<<NTOK, 256>>>(y2, h, ln_w + (size_t)l * DMODEL, ln_b + (size_t)l * DMODEL,
                                ahi, alo);
    }

    // ---- head ----
    head_kernel<<<NTOK, 256>>>(h, fn_w, fn_b, lo_w, lo_b, out);
    (void)in_sizes; (void)n_in; (void)out_size;
}